// round 10
// baseline (speedup 1.0000x reference)
#include <cuda_runtime.h>
#include <cuda_bf16.h>
#include <math.h>
#include <stdint.h>

// ---------------------------------------------------------------------------
// DNABERT2-style encoder forward. 3xTF32 tensor-core GEMMs + fp32 flash attn.
// B=1, L=2048, E=768, H=12, HD=64, NL=4, FFN=2048, V=4096
// ---------------------------------------------------------------------------

#define L_   2048
#define E_   768
#define H_   12
#define HD_  64
#define NL_  4
#define FFN_ 2048
#define V_   4096
#define EPS_ 1e-5f

// -------------------- scratch (static device globals; no allocation) -------
__device__ float g_x   [L_ * E_];
__device__ float g_h   [L_ * E_];
__device__ float g_tmp [L_ * E_];
__device__ float g_qkv [L_ * 3 * E_];
__device__ float g_u   [L_ * 2 * FFN_];
__device__ float g_gg  [L_ * FFN_];

// -------------------- helpers ----------------------------------------------
__device__ __forceinline__ float gelu_exact(float x) {
    return 0.5f * x * (1.0f + erff(x * 0.70710678118654752440f));
}

__device__ __forceinline__ float to_tf32(float x) {
    asm("cvt.rna.tf32.f32 %0, %1;" : "=f"(x) : "f"(x));
    return x;
}

__device__ __forceinline__ float2 split_tf32(float x) {
    float hi = to_tf32(x);
    float lo = to_tf32(x - hi);
    return make_float2(hi, lo);
}

__device__ __forceinline__ void mma_tf32(float* c, const uint32_t* a, const uint32_t* b) {
    asm volatile(
        "mma.sync.aligned.m16n8k8.row.col.f32.tf32.tf32.f32 "
        "{%0,%1,%2,%3}, {%4,%5,%6,%7}, {%8,%9}, {%0,%1,%2,%3};\n"
        : "+f"(c[0]), "+f"(c[1]), "+f"(c[2]), "+f"(c[3])
        : "r"(a[0]), "r"(a[1]), "r"(a[2]), "r"(a[3]), "r"(b[0]), "r"(b[1]));
}

// -------------------- embedding gather --------------------------------------
__global__ void embed_kernel(const int* __restrict__ tokens,
                             const float* __restrict__ embed,
                             float* __restrict__ x) {
    int idx = blockIdx.x * blockDim.x + threadIdx.x;
    if (idx >= L_ * E_) return;
    int l = idx / E_;
    int e = idx - l * E_;
    x[idx] = embed[(long)tokens[l] * E_ + e];
}

// -------------------- layernorm (one block per token) -----------------------
__global__ void layernorm_kernel(const float* __restrict__ x,
                                 const float* __restrict__ g,
                                 const float* __restrict__ b,
                                 float* __restrict__ y) {
    __shared__ float red[32];
    int row = blockIdx.x;
    int tid = threadIdx.x;             // 256 threads
    const float* xr = x + (long)row * E_;
    float v[3];
    #pragma unroll
    for (int i = 0; i < 3; i++) v[i] = xr[tid + i * 256];

    float s = v[0] + v[1] + v[2];
    #pragma unroll
    for (int o = 16; o > 0; o >>= 1) s += __shfl_xor_sync(0xffffffffu, s, o);
    if ((tid & 31) == 0) red[tid >> 5] = s;
    __syncthreads();
    float mean = 0.f;
    #pragma unroll
    for (int i = 0; i < 8; i++) mean += red[i];
    mean *= (1.0f / E_);
    __syncthreads();

    float sq = 0.f;
    #pragma unroll
    for (int i = 0; i < 3; i++) { float d = v[i] - mean; sq += d * d; }
    #pragma unroll
    for (int o = 16; o > 0; o >>= 1) sq += __shfl_xor_sync(0xffffffffu, sq, o);
    if ((tid & 31) == 0) red[tid >> 5] = sq;
    __syncthreads();
    float var = 0.f;
    #pragma unroll
    for (int i = 0; i < 8; i++) var += red[i];
    var *= (1.0f / E_);
    float inv = rsqrtf(var + EPS_);

    float* yr = y + (long)row * E_;
    #pragma unroll
    for (int i = 0; i < 3; i++) {
        int e = tid + i * 256;
        yr[e] = (v[i] - mean) * inv * g[e] + b[e];
    }
}

// -------------------- GEGLU -------------------------------------------------
__global__ void geglu_kernel(const float* __restrict__ u, float* __restrict__ o) {
    int idx = blockIdx.x * blockDim.x + threadIdx.x;
    if (idx >= L_ * FFN_) return;
    int l = idx / FFN_;
    int f = idx - l * FFN_;
    float a = u[(long)l * (2 * FFN_) + f];
    float g = u[(long)l * (2 * FFN_) + FFN_ + f];
    o[idx] = a * gelu_exact(g);
}

// -------------------- fused flash attention (256 threads, vector LDS) -------
// grid = (L/64, H). Q block 64 rows, K/V blocks of 32 keys.
// Thread map: ty = tid>>3 (0..31, 2 rows each), tx = tid&7.
#define FBM 64
#define FBN 32

__global__ __launch_bounds__(256, 2)
void flash_attn_kernel(const float* __restrict__ qkv,
                       const int* __restrict__ mask,
                       float* __restrict__ o) {
    __shared__ float Qs[HD_][FBM + 4];   // [d][m], scaled; row 272B (16B-mult)
    __shared__ float Ks[HD_][FBN + 4];   // [d][n]; row 144B (16B-mult)
    __shared__ float Vs[FBN][HD_ + 4];   // [k][d]; row 272B
    __shared__ float Ps[FBM][FBN + 1];   // [m][k]
    __shared__ float kp[FBN];

    int qb  = blockIdx.x;
    int h   = blockIdx.y;
    int tid = threadIdx.x;      // 0..255
    int ty  = tid >> 3;         // 0..31 -> rows ty*2, ty*2+1
    int tx  = tid & 7;          // 0..7

    float slope = (h < 8) ? exp2f(-(float)(h + 1))
                          : exp2f(-0.5f * (float)(2 * (h - 8) + 1));
    const float scale = 0.125f;

    // load Q block (64x64), scaled, transposed into Qs[d][m]
    #pragma unroll
    for (int r = 0; r < 4; r++) {
        int idx = tid + r * 256;            // 0..1023
        int m = idx >> 4;                   // 0..63
        int d4 = idx & 15;                  // 0..15
        float4 q4 = *(const float4*)(qkv + (long)(qb * FBM + m) * (3 * E_)
                                     + h * HD_ + d4 * 4);
        Qs[d4 * 4 + 0][m] = q4.x * scale;
        Qs[d4 * 4 + 1][m] = q4.y * scale;
        Qs[d4 * 4 + 2][m] = q4.z * scale;
        Qs[d4 * 4 + 3][m] = q4.w * scale;
    }

    float acc[2][8] = {};
    float mi[2], li[2];
    #pragma unroll
    for (int i = 0; i < 2; i++) { mi[i] = -1e30f; li[i] = 0.f; }

    for (int kb = 0; kb < L_ / FBN; kb++) {
        // load K (transposed) and V (direct) for this key block
        #pragma unroll
        for (int r = 0; r < 2; r++) {
            int idx = tid + r * 256;        // 0..511
            int n = idx >> 4;               // 0..31
            int d4 = idx & 15;
            const float* kb_ = qkv + (long)(kb * FBN + n) * (3 * E_) + E_ + h * HD_;
            float4 k4 = *(const float4*)(kb_ + d4 * 4);
            Ks[d4 * 4 + 0][n] = k4.x; Ks[d4 * 4 + 1][n] = k4.y;
            Ks[d4 * 4 + 2][n] = k4.z; Ks[d4 * 4 + 3][n] = k4.w;
            const float* vb_ = qkv + (long)(kb * FBN + n) * (3 * E_) + 2 * E_ + h * HD_;
            *(float4*)&Vs[n][d4 * 4] = *(const float4*)(vb_ + d4 * 4);
        }
        if (tid < FBN) kp[tid] = (mask[kb * FBN + tid] == 0) ? 1.0f : 0.0f;
        __syncthreads();

        // S = (scaled Q) K^T, 2x4 per thread, vector smem reads
        float S[2][4] = {};
        #pragma unroll 8
        for (int d = 0; d < HD_; d++) {
            float2 ra = *(const float2*)&Qs[d][ty * 2];
            float4 rb = *(const float4*)&Ks[d][tx * 4];
            S[0][0] = fmaf(ra.x, rb.x, S[0][0]);
            S[0][1] = fmaf(ra.x, rb.y, S[0][1]);
            S[0][2] = fmaf(ra.x, rb.z, S[0][2]);
            S[0][3] = fmaf(ra.x, rb.w, S[0][3]);
            S[1][0] = fmaf(ra.y, rb.x, S[1][0]);
            S[1][1] = fmaf(ra.y, rb.y, S[1][1]);
            S[1][2] = fmaf(ra.y, rb.z, S[1][2]);
            S[1][3] = fmaf(ra.y, rb.w, S[1][3]);
        }
        // bias: alibi + key padding
        #pragma unroll
        for (int i = 0; i < 2; i++) {
            int m = qb * FBM + ty * 2 + i;
            #pragma unroll
            for (int j = 0; j < 4; j++) {
                int n = kb * FBN + tx * 4 + j;
                S[i][j] += slope * (float)(n - m) + kp[tx * 4 + j];
            }
        }
        // online softmax (row group = 8 consecutive lanes, same ty)
        #pragma unroll
        for (int i = 0; i < 2; i++) {
            float mx = fmaxf(fmaxf(S[i][0], S[i][1]), fmaxf(S[i][2], S[i][3]));
            #pragma unroll
            for (int o2 = 1; o2 < 8; o2 <<= 1)
                mx = fmaxf(mx, __shfl_xor_sync(0xffffffffu, mx, o2));
            float nm = fmaxf(mi[i], mx);
            float corr = __expf(mi[i] - nm);
            float s = 0.f;
            #pragma unroll
            for (int j = 0; j < 4; j++) { S[i][j] = __expf(S[i][j] - nm); s += S[i][j]; }
            #pragma unroll
            for (int o2 = 1; o2 < 8; o2 <<= 1)
                s += __shfl_xor_sync(0xffffffffu, s, o2);
            li[i] = li[i] * corr + s;
            mi[i] = nm;
            #pragma unroll
            for (int j = 0; j < 8; j++) acc[i][j] *= corr;
            #pragma unroll
            for (int j = 0; j < 4; j++) Ps[ty * 2 + i][tx * 4 + j] = S[i][j];
        }
        __syncthreads();

        // O += P @ V  (rows ty*2+i, dims tx*8+j), vector V reads
        #pragma unroll 4
        for (int k = 0; k < FBN; k++) {
            float pa0 = Ps[ty * 2 + 0][k];
            float pa1 = Ps[ty * 2 + 1][k];
            float4 v0 = *(const float4*)&Vs[k][tx * 8];
            float4 v1 = *(const float4*)&Vs[k][tx * 8 + 4];
            acc[0][0] = fmaf(pa0, v0.x, acc[0][0]);
            acc[0][1] = fmaf(pa0, v0.y, acc[0][1]);
            acc[0][2] = fmaf(pa0, v0.z, acc[0][2]);
            acc[0][3] = fmaf(pa0, v0.w, acc[0][3]);
            acc[0][4] = fmaf(pa0, v1.x, acc[0][4]);
            acc[0][5] = fmaf(pa0, v1.y, acc[0][5]);
            acc[0][6] = fmaf(pa0, v1.z, acc[0][6]);
            acc[0][7] = fmaf(pa0, v1.w, acc[0][7]);
            acc[1][0] = fmaf(pa1, v0.x, acc[1][0]);
            acc[1][1] = fmaf(pa1, v0.y, acc[1][1]);
            acc[1][2] = fmaf(pa1, v0.z, acc[1][2]);
            acc[1][3] = fmaf(pa1, v0.w, acc[1][3]);
            acc[1][4] = fmaf(pa1, v1.x, acc[1][4]);
            acc[1][5] = fmaf(pa1, v1.y, acc[1][5]);
            acc[1][6] = fmaf(pa1, v1.z, acc[1][6]);
            acc[1][7] = fmaf(pa1, v1.w, acc[1][7]);
        }
        __syncthreads();
    }

    // normalize and write (vector stores)
    #pragma unroll
    for (int i = 0; i < 2; i++) {
        int m = qb * FBM + ty * 2 + i;
        float inv = 1.0f / li[i];
        float4 w0 = make_float4(acc[i][0] * inv, acc[i][1] * inv,
                                acc[i][2] * inv, acc[i][3] * inv);
        float4 w1 = make_float4(acc[i][4] * inv, acc[i][5] * inv,
                                acc[i][6] * inv, acc[i][7] * inv);
        *(float4*)(o + (long)m * E_ + h * HD_ + tx * 8)     = w0;
        *(float4*)(o + (long)m * E_ + h * HD_ + tx * 8 + 4) = w1;
    }
}

// -------------------- 3xTF32 tensor-core GEMM -------------------------------
// C[m,n] = sum_k A[m,k] * B[n,k]   (B is (N,K) row-major: "x @ W^T")
// Error-compensated: A=Ah+Al, B=Bh+Bl (tf32 splits), packed (hi,lo) in float2
// smem so each fragment load is one LDS.64.
// C ≈ Ah·Bh + Ah·Bl + Al·Bh  (dropped Al·Bl term is O(2^-22)).
// epi: 0 = +bias, 1 = +bias+residual, 2 = gelu(+bias)
// Requirements: M % 128 == 0, N % 64 == 0, K % 16 == 0 (all shapes satisfy).
#define TBM 128
#define TBN 64
#define TBK 16

__global__ __launch_bounds__(256, 2)
void gemm_tf32_kernel(const float* __restrict__ A,
                      const float* __restrict__ B,
                      const float* __restrict__ bias,
                      const float* __restrict__ resid,
                      float* __restrict__ C,
                      int M, int N, int K, int epi) {
    __shared__ float2 As2[2][TBK][TBM + 4];   // (hi, lo)
    __shared__ float2 Bs2[2][TBK][TBN + 4];

    int tid  = threadIdx.x;
    int lane = tid & 31;
    int wid  = tid >> 5;           // 0..7
    int wm   = (wid & 3) * 32;     // warp row offset in tile
    int wn   = (wid >> 2) * 32;    // warp col offset in tile
    int g    = lane >> 2;          // 0..7
    int tg   = lane & 3;           // 0..3

    int m0 = blockIdx.y * TBM;
    int n0 = blockIdx.x * TBN;

    int arow = tid >> 2;           // 0..63 (A rows arow, arow+64)
    int ac4  = (tid & 3) * 4;      // k-offset within tile
    int brow = tid >> 2;           // 0..63 (B row n)
    int bc4  = (tid & 3) * 4;

    float acc[2][4][4];
    #pragma unroll
    for (int i = 0; i < 2; i++)
        #pragma unroll
        for (int j = 0; j < 4; j++)
            #pragma unroll
            for (int q = 0; q < 4; q++) acc[i][j][q] = 0.f;

    const int KT = K / TBK;

    // ---- load tile 0 ----
    {
        #pragma unroll
        for (int r = 0; r < 2; r++) {
            int m = arow + r * 64;
            float4 a4 = *(const float4*)(A + (long)(m0 + m) * K + ac4);
            As2[0][ac4 + 0][m] = split_tf32(a4.x);
            As2[0][ac4 + 1][m] = split_tf32(a4.y);
            As2[0][ac4 + 2][m] = split_tf32(a4.z);
            As2[0][ac4 + 3][m] = split_tf32(a4.w);
        }
        float4 b4 = *(const float4*)(B + (long)(n0 + brow) * K + bc4);
        Bs2[0][bc4 + 0][brow] = split_tf32(b4.x);
        Bs2[0][bc4 + 1][brow] = split_tf32(b4.y);
        Bs2[0][bc4 + 2][brow] = split_tf32(b4.z);
        Bs2[0][bc4 + 3][brow] = split_tf32(b4.w);
    }
    __syncthreads();

    for (int kt = 0; kt < KT; kt++) {
        int cur = kt & 1;

        // prefetch next tile into registers
        float4 na0, na1, nb;
        if (kt + 1 < KT) {
            int k0 = (kt + 1) * TBK;
            na0 = *(const float4*)(A + (long)(m0 + arow) * K + k0 + ac4);
            na1 = *(const float4*)(A + (long)(m0 + arow + 64) * K + k0 + ac4);
            nb  = *(const float4*)(B + (long)(n0 + brow) * K + k0 + bc4);
        }

        // compute on current tile
        #pragma unroll
        for (int kk = 0; kk < TBK; kk += 8) {
            uint32_t ah[2][4], al[2][4], bh[4][2], bl[4][2];
            #pragma unroll
            for (int mt = 0; mt < 2; mt++) {
                int m = wm + mt * 16 + g;
                float2 a0 = As2[cur][kk + tg    ][m];
                float2 a1 = As2[cur][kk + tg    ][m + 8];
                float2 a2 = As2[cur][kk + tg + 4][m];
                float2 a3 = As2[cur][kk + tg + 4][m + 8];
                ah[mt][0] = __float_as_uint(a0.x); al[mt][0] = __float_as_uint(a0.y);
                ah[mt][1] = __float_as_uint(a1.x); al[mt][1] = __float_as_uint(a1.y);
                ah[mt][2] = __float_as_uint(a2.x); al[mt][2] = __float_as_uint(a2.y);
                ah[mt][3] = __float_as_uint(a3.x); al[mt][3] = __float_as_uint(a3.y);
            }
            #pragma unroll
            for (int nt = 0; nt < 4; nt++) {
                int n = wn + nt * 8 + g;
                float2 b0 = Bs2[cur][kk + tg    ][n];
                float2 b1 = Bs2[cur][kk + tg + 4][n];
                bh[nt][0] = __float_as_uint(b0.x); bl[nt][0] = __float_as_uint(b0.y);
                bh[nt][1] = __float_as_uint(b1.x); bl[nt][1] = __float_as_uint(b1.y);
            }
            #pragma unroll
            for (int mt = 0; mt < 2; mt++)
                #pragma unroll
                for (int nt = 0; nt < 4; nt++) {
                    mma_tf32(acc[mt][nt], al[mt], bh[nt]);   // Al*Bh (small)
                    mma_tf32(acc[mt][nt], ah[mt], bl[nt]);   // Ah*Bl (small)
                    mma_tf32(acc[mt][nt], ah[mt], bh[nt]);   // Ah*Bh (main)
                }
        }

        // store prefetched tile into the other buffer
        if (kt + 1 < KT) {
            int nxt = cur ^ 1;
            As2[nxt][ac4 + 0][arow] = split_tf32(na0.x);
            As2[nxt][ac4 + 1][arow] = split_tf32(na0.y);
            As2[nxt][ac4 + 2][arow] = split_tf32(na0.z);
            As2[nxt][ac4 + 3][arow] = split_tf32(na0.w);
            As2[nxt][ac4 + 0][arow + 64] = split_tf32(na1.x);
            As2[nxt][ac4 + 1][arow + 64] = split_tf32(na1.y);
            As2[nxt][ac4 + 2][arow + 64] = split_tf32(na1.z);
            As2[nxt][ac4 + 3][arow + 64] = split_tf32(na1.w);
            Bs2[nxt][bc4 + 0][brow] = split_tf32(nb.x);
            Bs2[nxt][bc4 + 1][brow] = split_tf32(nb.y);
            Bs2[nxt][bc4 + 2][brow] = split_tf32(nb.z);
            Bs2[nxt][bc4 + 3][brow] = split_tf32(nb.w);
            __syncthreads();
        }
    }

    // ---- epilogue ----
    #pragma unroll
    for (int mt = 0; mt < 2; mt++) {
        #pragma unroll
        for (int nt = 0; nt < 4; nt++) {
            int c = n0 + wn + nt * 8 + 2 * tg;
            float b0 = bias[c], b1 = bias[c + 1];
            #pragma unroll
            for (int hf = 0; hf < 2; hf++) {
                int r = m0 + wm + mt * 16 + g + hf * 8;
                float v0 = acc[mt][nt][hf * 2 + 0] + b0;
                float v1 = acc[mt][nt][hf * 2 + 1] + b1;
                if (epi == 1) {
                    v0 += resid[(long)r * N + c];
                    v1 += resid[(long)r * N + c + 1];
                }
                if (epi == 2) { v0 = gelu_exact(v0); v1 = gelu_exact(v1); }
                *(float2*)(C + (long)r * N + c) = make_float2(v0, v1);
            }
        }
    }
}

// ---------------------------------------------------------------------------
extern "C" void kernel_launch(void* const* d_in, const int* in_sizes, int n_in,
                              void* d_out, int out_size) {
    const int*   tokens   = (const int*)  d_in[0];
    const int*   attmask  = (const int*)  d_in[1];
    const float* embed    = (const float*)d_in[2];
    const float* norm1_g  = (const float*)d_in[3];
    const float* norm1_b  = (const float*)d_in[4];
    const float* in_w     = (const float*)d_in[5];
    const float* in_b     = (const float*)d_in[6];
    const float* out_w    = (const float*)d_in[7];
    const float* out_b    = (const float*)d_in[8];
    const float* ffn_g    = (const float*)d_in[9];
    const float* ffn_bt   = (const float*)d_in[10];
    const float* ffn_w1   = (const float*)d_in[11];
    const float* ffn_b1   = (const float*)d_in[12];
    const float* ffn_w2   = (const float*)d_in[13];
    const float* ffn_b2   = (const float*)d_in[14];
    const float* fin_g    = (const float*)d_in[15];
    const float* fin_b    = (const float*)d_in[16];
    const float* mlm_w1   = (const float*)d_in[17];
    const float* mlm_b1   = (const float*)d_in[18];
    const float* mlm_g    = (const float*)d_in[19];
    const float* mlm_bt   = (const float*)d_in[20];
    const float* mlm_w2   = (const float*)d_in[21];
    const float* mlm_b2   = (const float*)d_in[22];
    float* out = (float*)d_out;

    float *x, *h, *tmp, *qkv, *u, *gg;
    cudaGetSymbolAddress((void**)&x,   g_x);
    cudaGetSymbolAddress((void**)&h,   g_h);
    cudaGetSymbolAddress((void**)&tmp, g_tmp);
    cudaGetSymbolAddress((void**)&qkv, g_qkv);
    cudaGetSymbolAddress((void**)&u,   g_u);
    cudaGetSymbolAddress((void**)&gg,  g_gg);

    embed_kernel<<<(L_ * E_ + 255) / 256, 256>>>(tokens, embed, x);

    for (int i = 0; i < NL_; i++) {
        // ---- attention ----
        layernorm_kernel<<<L_, 256>>>(x, norm1_g + i * E_, norm1_b + i * E_, h);

        gemm_tf32_kernel<<<dim3(3 * E_ / TBN, L_ / TBM), 256>>>(
            h, in_w + (long)i * 3 * E_ * E_, in_b + (long)i * 3 * E_,
            nullptr, qkv, L_, 3 * E_, E_, 0);

        flash_attn_kernel<<<dim3(L_ / FBM, H_), 256>>>(qkv, attmask, tmp);

        gemm_tf32_kernel<<<dim3(E_ / TBN, L_ / TBM), 256>>>(
            tmp, out_w + (long)i * E_ * E_, out_b + (long)i * E_,
            x, x, L_, E_, E_, 1);

        // ---- GEGLU FFN ----
        layernorm_kernel<<<L_, 256>>>(x, ffn_g + i * E_, ffn_bt + i * E_, h);

        gemm_tf32_kernel<<<dim3(2 * FFN_ / TBN, L_ / TBM), 256>>>(
            h, ffn_w1 + (long)i * 2 * FFN_ * E_, ffn_b1 + (long)i * 2 * FFN_,
            nullptr, u, L_, 2 * FFN_, E_, 0);

        geglu_kernel<<<(L_ * FFN_ + 255) / 256, 256>>>(u, gg);

        gemm_tf32_kernel<<<dim3(E_ / TBN, L_ / TBM), 256>>>(
            gg, ffn_w2 + (long)i * E_ * FFN_, ffn_b2 + (long)i * E_,
            x, x, L_, E_, FFN_, 1);
    }

    // ---- MLM head ----
    layernorm_kernel<<<L_, 256>>>(x, fin_g, fin_b, h);

    gemm_tf32_kernel<<<dim3(E_ / TBN, L_ / TBM), 256>>>(
        h, mlm_w1, mlm_b1, nullptr, tmp, L_, E_, E_, 2);

    layernorm_kernel<<<L_, 256>>>(tmp, mlm_g, mlm_bt, h);

    gemm_tf32_kernel<<<dim3(V_ / TBN, L_ / TBM), 256>>>(
        h, mlm_w2, mlm_b2, nullptr, out, L_, V_, E_, 0);
}

// round 12
// speedup vs baseline: 1.2417x; 1.2417x over previous
#include <cuda_runtime.h>
#include <cuda_bf16.h>
#include <math.h>
#include <stdint.h>

// ---------------------------------------------------------------------------
// DNABERT2-style encoder forward. 3xTF32 tensor-core GEMMs + fp32 flash attn.
// B=1, L=2048, E=768, H=12, HD=64, NL=4, FFN=2048, V=4096
// ---------------------------------------------------------------------------

#define L_   2048
#define E_   768
#define H_   12
#define HD_  64
#define NL_  4
#define FFN_ 2048
#define V_   4096
#define EPS_ 1e-5f

// -------------------- scratch (static device globals; no allocation) -------
__device__ float g_x   [L_ * E_];
__device__ float g_h   [L_ * E_];
__device__ float g_tmp [L_ * E_];
__device__ float g_qkv [L_ * 3 * E_];
__device__ float g_u   [L_ * 2 * FFN_];
__device__ float g_gg  [L_ * FFN_];

// -------------------- helpers ----------------------------------------------
__device__ __forceinline__ float gelu_exact(float x) {
    return 0.5f * x * (1.0f + erff(x * 0.70710678118654752440f));
}

__device__ __forceinline__ float to_tf32(float x) {
    asm("cvt.rna.tf32.f32 %0, %1;" : "=f"(x) : "f"(x));
    return x;
}

__device__ __forceinline__ void split_tf32(float x, float& hi, float& lo) {
    hi = to_tf32(x);
    lo = to_tf32(x - hi);
}

__device__ __forceinline__ void mma_tf32(float* c, const uint32_t* a, const uint32_t* b) {
    asm volatile(
        "mma.sync.aligned.m16n8k8.row.col.f32.tf32.tf32.f32 "
        "{%0,%1,%2,%3}, {%4,%5,%6,%7}, {%8,%9}, {%0,%1,%2,%3};\n"
        : "+f"(c[0]), "+f"(c[1]), "+f"(c[2]), "+f"(c[3])
        : "r"(a[0]), "r"(a[1]), "r"(a[2]), "r"(a[3]), "r"(b[0]), "r"(b[1]));
}

// -------------------- embedding gather --------------------------------------
__global__ void embed_kernel(const int* __restrict__ tokens,
                             const float* __restrict__ embed,
                             float* __restrict__ x) {
    int idx = blockIdx.x * blockDim.x + threadIdx.x;
    if (idx >= L_ * E_) return;
    int l = idx / E_;
    int e = idx - l * E_;
    x[idx] = embed[(long)tokens[l] * E_ + e];
}

// -------------------- layernorm (one block per token) -----------------------
__global__ void layernorm_kernel(const float* __restrict__ x,
                                 const float* __restrict__ g,
                                 const float* __restrict__ b,
                                 float* __restrict__ y) {
    __shared__ float red[32];
    int row = blockIdx.x;
    int tid = threadIdx.x;             // 256 threads
    const float* xr = x + (long)row * E_;
    float v[3];
    #pragma unroll
    for (int i = 0; i < 3; i++) v[i] = xr[tid + i * 256];

    float s = v[0] + v[1] + v[2];
    #pragma unroll
    for (int o = 16; o > 0; o >>= 1) s += __shfl_xor_sync(0xffffffffu, s, o);
    if ((tid & 31) == 0) red[tid >> 5] = s;
    __syncthreads();
    float mean = 0.f;
    #pragma unroll
    for (int i = 0; i < 8; i++) mean += red[i];
    mean *= (1.0f / E_);
    __syncthreads();

    float sq = 0.f;
    #pragma unroll
    for (int i = 0; i < 3; i++) { float d = v[i] - mean; sq += d * d; }
    #pragma unroll
    for (int o = 16; o > 0; o >>= 1) sq += __shfl_xor_sync(0xffffffffu, sq, o);
    if ((tid & 31) == 0) red[tid >> 5] = sq;
    __syncthreads();
    float var = 0.f;
    #pragma unroll
    for (int i = 0; i < 8; i++) var += red[i];
    var *= (1.0f / E_);
    float inv = rsqrtf(var + EPS_);

    float* yr = y + (long)row * E_;
    #pragma unroll
    for (int i = 0; i < 3; i++) {
        int e = tid + i * 256;
        yr[e] = (v[i] - mean) * inv * g[e] + b[e];
    }
}

// -------------------- GEGLU -------------------------------------------------
__global__ void geglu_kernel(const float* __restrict__ u, float* __restrict__ o) {
    int idx = blockIdx.x * blockDim.x + threadIdx.x;
    if (idx >= L_ * FFN_) return;
    int l = idx / FFN_;
    int f = idx - l * FFN_;
    float a = u[(long)l * (2 * FFN_) + f];
    float g = u[(long)l * (2 * FFN_) + FFN_ + f];
    o[idx] = a * gelu_exact(g);
}

// -------------------- fused flash attention (128 thr, vector LDS) -----------
// grid = (L/64, H). 128 threads. Q block 64 rows, K/V blocks of 32 keys.
// ty = tid>>3 (0..15, 4 rows each), tx = tid&7 (S: 4 cols, PV: 8 dims).
// All hot-loop smem reads are LDS.128; P stored transposed for the PV loop.
#define FBM 64
#define FBN 32

__global__ __launch_bounds__(128, 2)
void flash_attn_kernel(const float* __restrict__ qkv,
                       const int* __restrict__ mask,
                       float* __restrict__ o) {
    __shared__ float Qs[HD_][FBM + 4];   // [d][m], scaled; 272B rows
    __shared__ float Ks[HD_][FBN + 4];   // [d][n]; 144B rows (16B mult)
    __shared__ float Vs[FBN][HD_ + 4];   // [k][d]; 272B rows
    __shared__ float PsT[FBN][FBM + 4];  // [k][m] (transposed!)
    __shared__ float kp[FBN];

    int qb  = blockIdx.x;
    int h   = blockIdx.y;
    int tid = threadIdx.x;      // 0..127
    int ty  = tid >> 3;         // 0..15
    int tx  = tid & 7;          // 0..7

    float slope = (h < 8) ? exp2f(-(float)(h + 1))
                          : exp2f(-0.5f * (float)(2 * (h - 8) + 1));
    const float scale = 0.125f;

    // load Q block (64x64), scaled, transposed into Qs[d][m]
    #pragma unroll
    for (int r = 0; r < 8; r++) {
        int idx = tid + r * 128;            // 0..1023
        int m = idx >> 4;                   // 0..63
        int d4 = idx & 15;                  // 0..15
        float4 q4 = *(const float4*)(qkv + (long)(qb * FBM + m) * (3 * E_)
                                     + h * HD_ + d4 * 4);
        Qs[d4 * 4 + 0][m] = q4.x * scale;
        Qs[d4 * 4 + 1][m] = q4.y * scale;
        Qs[d4 * 4 + 2][m] = q4.z * scale;
        Qs[d4 * 4 + 3][m] = q4.w * scale;
    }

    float acc[4][8] = {};
    float mi[4], li[4];
    #pragma unroll
    for (int i = 0; i < 4; i++) { mi[i] = -1e30f; li[i] = 0.f; }

    for (int kb = 0; kb < L_ / FBN; kb++) {
        // load K (transposed) and V (direct) for this key block
        #pragma unroll
        for (int r = 0; r < 4; r++) {
            int idx = tid + r * 128;        // 0..511
            int n = idx >> 4;               // 0..31
            int d4 = idx & 15;
            const float* kb_ = qkv + (long)(kb * FBN + n) * (3 * E_) + E_ + h * HD_;
            float4 k4 = *(const float4*)(kb_ + d4 * 4);
            Ks[d4 * 4 + 0][n] = k4.x; Ks[d4 * 4 + 1][n] = k4.y;
            Ks[d4 * 4 + 2][n] = k4.z; Ks[d4 * 4 + 3][n] = k4.w;
            const float* vb_ = qkv + (long)(kb * FBN + n) * (3 * E_) + 2 * E_ + h * HD_;
            *(float4*)&Vs[n][d4 * 4] = *(const float4*)(vb_ + d4 * 4);
        }
        if (tid < FBN) kp[tid] = (mask[kb * FBN + tid] == 0) ? 1.0f : 0.0f;
        __syncthreads();

        // S = (scaled Q) K^T, 4x4 per thread — vector LDS (2 x LDS.128 per d)
        float S[4][4] = {};
        #pragma unroll 8
        for (int d = 0; d < HD_; d++) {
            float4 ra = *(const float4*)&Qs[d][ty * 4];
            float4 rb = *(const float4*)&Ks[d][tx * 4];
            S[0][0] = fmaf(ra.x, rb.x, S[0][0]);
            S[0][1] = fmaf(ra.x, rb.y, S[0][1]);
            S[0][2] = fmaf(ra.x, rb.z, S[0][2]);
            S[0][3] = fmaf(ra.x, rb.w, S[0][3]);
            S[1][0] = fmaf(ra.y, rb.x, S[1][0]);
            S[1][1] = fmaf(ra.y, rb.y, S[1][1]);
            S[1][2] = fmaf(ra.y, rb.z, S[1][2]);
            S[1][3] = fmaf(ra.y, rb.w, S[1][3]);
            S[2][0] = fmaf(ra.z, rb.x, S[2][0]);
            S[2][1] = fmaf(ra.z, rb.y, S[2][1]);
            S[2][2] = fmaf(ra.z, rb.z, S[2][2]);
            S[2][3] = fmaf(ra.z, rb.w, S[2][3]);
            S[3][0] = fmaf(ra.w, rb.x, S[3][0]);
            S[3][1] = fmaf(ra.w, rb.y, S[3][1]);
            S[3][2] = fmaf(ra.w, rb.z, S[3][2]);
            S[3][3] = fmaf(ra.w, rb.w, S[3][3]);
        }
        // bias: alibi + key padding
        #pragma unroll
        for (int i = 0; i < 4; i++) {
            int m = qb * FBM + ty * 4 + i;
            #pragma unroll
            for (int j = 0; j < 4; j++) {
                int n = kb * FBN + tx * 4 + j;
                S[i][j] += slope * (float)(n - m) + kp[tx * 4 + j];
            }
        }
        // online softmax (row group = 8 lanes with same ty)
        #pragma unroll
        for (int i = 0; i < 4; i++) {
            float mx = fmaxf(fmaxf(S[i][0], S[i][1]), fmaxf(S[i][2], S[i][3]));
            #pragma unroll
            for (int o2 = 1; o2 < 8; o2 <<= 1)
                mx = fmaxf(mx, __shfl_xor_sync(0xffffffffu, mx, o2));
            float nm = fmaxf(mi[i], mx);
            float corr = __expf(mi[i] - nm);
            float s = 0.f;
            #pragma unroll
            for (int j = 0; j < 4; j++) { S[i][j] = __expf(S[i][j] - nm); s += S[i][j]; }
            #pragma unroll
            for (int o2 = 1; o2 < 8; o2 <<= 1)
                s += __shfl_xor_sync(0xffffffffu, s, o2);
            li[i] = li[i] * corr + s;
            mi[i] = nm;
            #pragma unroll
            for (int j = 0; j < 8; j++) acc[i][j] *= corr;
            #pragma unroll
            for (int j = 0; j < 4; j++) PsT[tx * 4 + j][ty * 4 + i] = S[i][j];
        }
        __syncthreads();

        // O += P @ V  (rows ty*4+i, dims tx*8+j) — 3 x LDS.128 per k
        #pragma unroll 4
        for (int k = 0; k < FBN; k++) {
            float4 pa = *(const float4*)&PsT[k][ty * 4];
            float4 v0 = *(const float4*)&Vs[k][tx * 8];
            float4 v1 = *(const float4*)&Vs[k][tx * 8 + 4];
            acc[0][0] = fmaf(pa.x, v0.x, acc[0][0]);
            acc[0][1] = fmaf(pa.x, v0.y, acc[0][1]);
            acc[0][2] = fmaf(pa.x, v0.z, acc[0][2]);
            acc[0][3] = fmaf(pa.x, v0.w, acc[0][3]);
            acc[0][4] = fmaf(pa.x, v1.x, acc[0][4]);
            acc[0][5] = fmaf(pa.x, v1.y, acc[0][5]);
            acc[0][6] = fmaf(pa.x, v1.z, acc[0][6]);
            acc[0][7] = fmaf(pa.x, v1.w, acc[0][7]);
            acc[1][0] = fmaf(pa.y, v0.x, acc[1][0]);
            acc[1][1] = fmaf(pa.y, v0.y, acc[1][1]);
            acc[1][2] = fmaf(pa.y, v0.z, acc[1][2]);
            acc[1][3] = fmaf(pa.y, v0.w, acc[1][3]);
            acc[1][4] = fmaf(pa.y, v1.x, acc[1][4]);
            acc[1][5] = fmaf(pa.y, v1.y, acc[1][5]);
            acc[1][6] = fmaf(pa.y, v1.z, acc[1][6]);
            acc[1][7] = fmaf(pa.y, v1.w, acc[1][7]);
            acc[2][0] = fmaf(pa.z, v0.x, acc[2][0]);
            acc[2][1] = fmaf(pa.z, v0.y, acc[2][1]);
            acc[2][2] = fmaf(pa.z, v0.z, acc[2][2]);
            acc[2][3] = fmaf(pa.z, v0.w, acc[2][3]);
            acc[2][4] = fmaf(pa.z, v1.x, acc[2][4]);
            acc[2][5] = fmaf(pa.z, v1.y, acc[2][5]);
            acc[2][6] = fmaf(pa.z, v1.z, acc[2][6]);
            acc[2][7] = fmaf(pa.z, v1.w, acc[2][7]);
            acc[3][0] = fmaf(pa.w, v0.x, acc[3][0]);
            acc[3][1] = fmaf(pa.w, v0.y, acc[3][1]);
            acc[3][2] = fmaf(pa.w, v0.z, acc[3][2]);
            acc[3][3] = fmaf(pa.w, v0.w, acc[3][3]);
            acc[3][4] = fmaf(pa.w, v1.x, acc[3][4]);
            acc[3][5] = fmaf(pa.w, v1.y, acc[3][5]);
            acc[3][6] = fmaf(pa.w, v1.z, acc[3][6]);
            acc[3][7] = fmaf(pa.w, v1.w, acc[3][7]);
        }
        __syncthreads();
    }

    // normalize and write (vector stores)
    #pragma unroll
    for (int i = 0; i < 4; i++) {
        int m = qb * FBM + ty * 4 + i;
        float inv = 1.0f / li[i];
        float4 w0 = make_float4(acc[i][0] * inv, acc[i][1] * inv,
                                acc[i][2] * inv, acc[i][3] * inv);
        float4 w1 = make_float4(acc[i][4] * inv, acc[i][5] * inv,
                                acc[i][6] * inv, acc[i][7] * inv);
        *(float4*)(o + (long)m * E_ + h * HD_ + tx * 8)     = w0;
        *(float4*)(o + (long)m * E_ + h * HD_ + tx * 8 + 4) = w1;
    }
}

// -------------------- 3xTF32 tensor-core GEMM (R7 layout, verified) ---------
// C[m,n] = sum_k A[m,k] * B[n,k]   (B is (N,K) row-major: "x @ W^T")
// C ≈ Ah·Bh + Ah·Bl + Al·Bh  (dropped Al·Bl term is O(2^-22)).
// epi: 0 = +bias, 1 = +bias+residual, 2 = gelu(+bias)
#define TBM 128
#define TBN 64
#define TBK 16

__global__ __launch_bounds__(256, 2)
void gemm_tf32_kernel(const float* __restrict__ A,
                      const float* __restrict__ B,
                      const float* __restrict__ bias,
                      const float* __restrict__ resid,
                      float* __restrict__ C,
                      int M, int N, int K, int epi) {
    __shared__ float Ah[2][TBK][TBM + 4];
    __shared__ float Al[2][TBK][TBM + 4];
    __shared__ float Bh[2][TBK][TBN + 4];
    __shared__ float Bl[2][TBK][TBN + 4];

    int tid  = threadIdx.x;
    int lane = tid & 31;
    int wid  = tid >> 5;           // 0..7
    int wm   = (wid & 3) * 32;     // warp row offset in tile
    int wn   = (wid >> 2) * 32;    // warp col offset in tile
    int g    = lane >> 2;          // 0..7
    int tg   = lane & 3;           // 0..3

    int m0 = blockIdx.y * TBM;
    int n0 = blockIdx.x * TBN;

    int arow = tid >> 2;           // 0..63 (A rows arow, arow+64)
    int ac4  = (tid & 3) * 4;      // k-offset within tile
    int brow = tid >> 2;           // 0..63 (B row n)
    int bc4  = (tid & 3) * 4;

    float acc[2][4][4];
    #pragma unroll
    for (int i = 0; i < 2; i++)
        #pragma unroll
        for (int j = 0; j < 4; j++)
            #pragma unroll
            for (int q = 0; q < 4; q++) acc[i][j][q] = 0.f;

    const int KT = K / TBK;

    // ---- load tile 0 ----
    {
        #pragma unroll
        for (int r = 0; r < 2; r++) {
            int m = arow + r * 64;
            float4 a4 = *(const float4*)(A + (long)(m0 + m) * K + ac4);
            float hi, lo;
            split_tf32(a4.x, hi, lo); Ah[0][ac4 + 0][m] = hi; Al[0][ac4 + 0][m] = lo;
            split_tf32(a4.y, hi, lo); Ah[0][ac4 + 1][m] = hi; Al[0][ac4 + 1][m] = lo;
            split_tf32(a4.z, hi, lo); Ah[0][ac4 + 2][m] = hi; Al[0][ac4 + 2][m] = lo;
            split_tf32(a4.w, hi, lo); Ah[0][ac4 + 3][m] = hi; Al[0][ac4 + 3][m] = lo;
        }
        float4 b4 = *(const float4*)(B + (long)(n0 + brow) * K + bc4);
        float hi, lo;
        split_tf32(b4.x, hi, lo); Bh[0][bc4 + 0][brow] = hi; Bl[0][bc4 + 0][brow] = lo;
        split_tf32(b4.y, hi, lo); Bh[0][bc4 + 1][brow] = hi; Bl[0][bc4 + 1][brow] = lo;
        split_tf32(b4.z, hi, lo); Bh[0][bc4 + 2][brow] = hi; Bl[0][bc4 + 2][brow] = lo;
        split_tf32(b4.w, hi, lo); Bh[0][bc4 + 3][brow] = hi; Bl[0][bc4 + 3][brow] = lo;
    }
    __syncthreads();

    for (int kt = 0; kt < KT; kt++) {
        int cur = kt & 1;

        // prefetch next tile into registers
        float4 na0, na1, nb;
        if (kt + 1 < KT) {
            int k0 = (kt + 1) * TBK;
            na0 = *(const float4*)(A + (long)(m0 + arow) * K + k0 + ac4);
            na1 = *(const float4*)(A + (long)(m0 + arow + 64) * K + k0 + ac4);
            nb  = *(const float4*)(B + (long)(n0 + brow) * K + k0 + bc4);
        }

        // compute on current tile
        #pragma unroll
        for (int kk = 0; kk < TBK; kk += 8) {
            uint32_t ah[2][4], al[2][4], bh[4][2], bl[4][2];
            #pragma unroll
            for (int mt = 0; mt < 2; mt++) {
                int m = wm + mt * 16 + g;
                ah[mt][0] = __float_as_uint(Ah[cur][kk + tg    ][m]);
                ah[mt][1] = __float_as_uint(Ah[cur][kk + tg    ][m + 8]);
                ah[mt][2] = __float_as_uint(Ah[cur][kk + tg + 4][m]);
                ah[mt][3] = __float_as_uint(Ah[cur][kk + tg + 4][m + 8]);
                al[mt][0] = __float_as_uint(Al[cur][kk + tg    ][m]);
                al[mt][1] = __float_as_uint(Al[cur][kk + tg    ][m + 8]);
                al[mt][2] = __float_as_uint(Al[cur][kk + tg + 4][m]);
                al[mt][3] = __float_as_uint(Al[cur][kk + tg + 4][m + 8]);
            }
            #pragma unroll
            for (int nt = 0; nt < 4; nt++) {
                int n = wn + nt * 8 + g;
                bh[nt][0] = __float_as_uint(Bh[cur][kk + tg    ][n]);
                bh[nt][1] = __float_as_uint(Bh[cur][kk + tg + 4][n]);
                bl[nt][0] = __float_as_uint(Bl[cur][kk + tg    ][n]);
                bl[nt][1] = __float_as_uint(Bl[cur][kk + tg + 4][n]);
            }
            #pragma unroll
            for (int mt = 0; mt < 2; mt++)
                #pragma unroll
                for (int nt = 0; nt < 4; nt++) {
                    mma_tf32(acc[mt][nt], al[mt], bh[nt]);   // Al*Bh (small)
                    mma_tf32(acc[mt][nt], ah[mt], bl[nt]);   // Ah*Bl (small)
                    mma_tf32(acc[mt][nt], ah[mt], bh[nt]);   // Ah*Bh (main)
                }
        }

        // store prefetched tile into the other buffer
        if (kt + 1 < KT) {
            int nxt = cur ^ 1;
            float hi, lo;
            split_tf32(na0.x, hi, lo); Ah[nxt][ac4 + 0][arow] = hi; Al[nxt][ac4 + 0][arow] = lo;
            split_tf32(na0.y, hi, lo); Ah[nxt][ac4 + 1][arow] = hi; Al[nxt][ac4 + 1][arow] = lo;
            split_tf32(na0.z, hi, lo); Ah[nxt][ac4 + 2][arow] = hi; Al[nxt][ac4 + 2][arow] = lo;
            split_tf32(na0.w, hi, lo); Ah[nxt][ac4 + 3][arow] = hi; Al[nxt][ac4 + 3][arow] = lo;
            split_tf32(na1.x, hi, lo); Ah[nxt][ac4 + 0][arow + 64] = hi; Al[nxt][ac4 + 0][arow + 64] = lo;
            split_tf32(na1.y, hi, lo); Ah[nxt][ac4 + 1][arow + 64] = hi; Al[nxt][ac4 + 1][arow + 64] = lo;
            split_tf32(na1.z, hi, lo); Ah[nxt][ac4 + 2][arow + 64] = hi; Al[nxt][ac4 + 2][arow + 64] = lo;
            split_tf32(na1.w, hi, lo); Ah[nxt][ac4 + 3][arow + 64] = hi; Al[nxt][ac4 + 3][arow + 64] = lo;
            split_tf32(nb.x, hi, lo);  Bh[nxt][bc4 + 0][brow] = hi; Bl[nxt][bc4 + 0][brow] = lo;
            split_tf32(nb.y, hi, lo);  Bh[nxt][bc4 + 1][brow] = hi; Bl[nxt][bc4 + 1][brow] = lo;
            split_tf32(nb.z, hi, lo);  Bh[nxt][bc4 + 2][brow] = hi; Bl[nxt][bc4 + 2][brow] = lo;
            split_tf32(nb.w, hi, lo);  Bh[nxt][bc4 + 3][brow] = hi; Bl[nxt][bc4 + 3][brow] = lo;
            __syncthreads();
        }
    }

    // ---- epilogue ----
    #pragma unroll
    for (int mt = 0; mt < 2; mt++) {
        #pragma unroll
        for (int nt = 0; nt < 4; nt++) {
            int c = n0 + wn + nt * 8 + 2 * tg;
            float b0 = bias[c], b1 = bias[c + 1];
            #pragma unroll
            for (int hf = 0; hf < 2; hf++) {
                int r = m0 + wm + mt * 16 + g + hf * 8;
                float v0 = acc[mt][nt][hf * 2 + 0] + b0;
                float v1 = acc[mt][nt][hf * 2 + 1] + b1;
                if (epi == 1) {
                    v0 += resid[(long)r * N + c];
                    v1 += resid[(long)r * N + c + 1];
                }
                if (epi == 2) { v0 = gelu_exact(v0); v1 = gelu_exact(v1); }
                *(float2*)(C + (long)r * N + c) = make_float2(v0, v1);
            }
        }
    }
}

// ---------------------------------------------------------------------------
extern "C" void kernel_launch(void* const* d_in, const int* in_sizes, int n_in,
                              void* d_out, int out_size) {
    const int*   tokens   = (const int*)  d_in[0];
    const int*   attmask  = (const int*)  d_in[1];
    const float* embed    = (const float*)d_in[2];
    const float* norm1_g  = (const float*)d_in[3];
    const float* norm1_b  = (const float*)d_in[4];
    const float* in_w     = (const float*)d_in[5];
    const float* in_b     = (const float*)d_in[6];
    const float* out_w    = (const float*)d_in[7];
    const float* out_b    = (const float*)d_in[8];
    const float* ffn_g    = (const float*)d_in[9];
    const float* ffn_bt   = (const float*)d_in[10];
    const float* ffn_w1   = (const float*)d_in[11];
    const float* ffn_b1   = (const float*)d_in[12];
    const float* ffn_w2   = (const float*)d_in[13];
    const float* ffn_b2   = (const float*)d_in[14];
    const float* fin_g    = (const float*)d_in[15];
    const float* fin_b    = (const float*)d_in[16];
    const float* mlm_w1   = (const float*)d_in[17];
    const float* mlm_b1   = (const float*)d_in[18];
    const float* mlm_g    = (const float*)d_in[19];
    const float* mlm_bt   = (const float*)d_in[20];
    const float* mlm_w2   = (const float*)d_in[21];
    const float* mlm_b2   = (const float*)d_in[22];
    float* out = (float*)d_out;

    float *x, *h, *tmp, *qkv, *u, *gg;
    cudaGetSymbolAddress((void**)&x,   g_x);
    cudaGetSymbolAddress((void**)&h,   g_h);
    cudaGetSymbolAddress((void**)&tmp, g_tmp);
    cudaGetSymbolAddress((void**)&qkv, g_qkv);
    cudaGetSymbolAddress((void**)&u,   g_u);
    cudaGetSymbolAddress((void**)&gg,  g_gg);

    embed_kernel<<<(L_ * E_ + 255) / 256, 256>>>(tokens, embed, x);

    for (int i = 0; i < NL_; i++) {
        // ---- attention ----
        layernorm_kernel<<<L_, 256>>>(x, norm1_g + i * E_, norm1_b + i * E_, h);

        gemm_tf32_kernel<<<dim3(3 * E_ / TBN, L_ / TBM), 256>>>(
            h, in_w + (long)i * 3 * E_ * E_, in_b + (long)i * 3 * E_,
            nullptr, qkv, L_, 3 * E_, E_, 0);

        flash_attn_kernel<<<dim3(L_ / FBM, H_), 128>>>(qkv, attmask, tmp);

        gemm_tf32_kernel<<<dim3(E_ / TBN, L_ / TBM), 256>>>(
            tmp, out_w + (long)i * E_ * E_, out_b + (long)i * E_,
            x, x, L_, E_, E_, 1);

        // ---- GEGLU FFN ----
        layernorm_kernel<<<L_, 256>>>(x, ffn_g + i * E_, ffn_bt + i * E_, h);

        gemm_tf32_kernel<<<dim3(2 * FFN_ / TBN, L_ / TBM), 256>>>(
            h, ffn_w1 + (long)i * 2 * FFN_ * E_, ffn_b1 + (long)i * 2 * FFN_,
            nullptr, u, L_, 2 * FFN_, E_, 0);

        geglu_kernel<<<(L_ * FFN_ + 255) / 256, 256>>>(u, gg);

        gemm_tf32_kernel<<<dim3(E_ / TBN, L_ / TBM), 256>>>(
            gg, ffn_w2 + (long)i * E_ * FFN_, ffn_b2 + (long)i * E_,
            x, x, L_, E_, FFN_, 1);
    }

    // ---- MLM head ----
    layernorm_kernel<<<L_, 256>>>(x, fin_g, fin_b, h);

    gemm_tf32_kernel<<<dim3(E_ / TBN, L_ / TBM), 256>>>(
        h, mlm_w1, mlm_b1, nullptr, tmp, L_, E_, E_, 2);

    layernorm_kernel<<<L_, 256>>>(tmp, mlm_g, mlm_bt, h);

    gemm_tf32_kernel<<<dim3(V_ / TBN, L_ / TBM), 256>>>(
        h, mlm_w2, mlm_b2, nullptr, out, L_, V_, E_, 0);
}

// round 16
// speedup vs baseline: 1.6808x; 1.3536x over previous
#include <cuda_runtime.h>
#include <cuda_bf16.h>
#include <math.h>
#include <stdint.h>

// ---------------------------------------------------------------------------
// DNABERT2-style encoder forward.
// GEMMs: mma.sync m16n8k16 BF16, 3-pass error-compensated (fp32=hi+lo).
// Attention: fp32 flash (verified R7 version).
// B=1, L=2048, E=768, H=12, HD=64, NL=4, FFN=2048, V=4096
// NOTE: tcgen05 is NOT available in this bench toolchain (ptxas targets
// sm_103 without the 'a' feature set) — legacy mma.sync is the tensor path.
// ---------------------------------------------------------------------------

#define L_   2048
#define E_   768
#define H_   12
#define HD_  64
#define NL_  4
#define FFN_ 2048
#define V_   4096
#define EPS_ 1e-5f

// -------------------- scratch (static device globals; no allocation) -------
__device__ float g_x   [L_ * E_];
__device__ float g_h   [L_ * E_];
__device__ float g_tmp [L_ * E_];
__device__ float g_qkv [L_ * 3 * E_];
__device__ float g_u   [L_ * 2 * FFN_];
__device__ float g_gg  [L_ * FFN_];

// -------------------- helpers ----------------------------------------------
__device__ __forceinline__ float gelu_exact(float x) {
    return 0.5f * x * (1.0f + erff(x * 0.70710678118654752440f));
}

__device__ __forceinline__ uint32_t pack_bf16(float x, float y) {
    __nv_bfloat162 t = __floats2bfloat162_rn(x, y);   // x -> low half
    return *(uint32_t*)&t;
}

__device__ __forceinline__ void mma_bf16(float* c, const uint32_t* a, const uint32_t* b) {
    asm volatile(
        "mma.sync.aligned.m16n8k16.row.col.f32.bf16.bf16.f32 "
        "{%0,%1,%2,%3}, {%4,%5,%6,%7}, {%8,%9}, {%0,%1,%2,%3};\n"
        : "+f"(c[0]), "+f"(c[1]), "+f"(c[2]), "+f"(c[3])
        : "r"(a[0]), "r"(a[1]), "r"(a[2]), "r"(a[3]), "r"(b[0]), "r"(b[1]));
}

// -------------------- embedding gather --------------------------------------
__global__ void embed_kernel(const int* __restrict__ tokens,
                             const float* __restrict__ embed,
                             float* __restrict__ x) {
    int idx = blockIdx.x * blockDim.x + threadIdx.x;
    if (idx >= L_ * E_) return;
    int l = idx / E_;
    int e = idx - l * E_;
    x[idx] = embed[(long)tokens[l] * E_ + e];
}

// -------------------- layernorm (one block per token) -----------------------
__global__ void layernorm_kernel(const float* __restrict__ x,
                                 const float* __restrict__ g,
                                 const float* __restrict__ b,
                                 float* __restrict__ y) {
    __shared__ float red[32];
    int row = blockIdx.x;
    int tid = threadIdx.x;             // 256 threads
    const float* xr = x + (long)row * E_;
    float v[3];
    #pragma unroll
    for (int i = 0; i < 3; i++) v[i] = xr[tid + i * 256];

    float s = v[0] + v[1] + v[2];
    #pragma unroll
    for (int o = 16; o > 0; o >>= 1) s += __shfl_xor_sync(0xffffffffu, s, o);
    if ((tid & 31) == 0) red[tid >> 5] = s;
    __syncthreads();
    float mean = 0.f;
    #pragma unroll
    for (int i = 0; i < 8; i++) mean += red[i];
    mean *= (1.0f / E_);
    __syncthreads();

    float sq = 0.f;
    #pragma unroll
    for (int i = 0; i < 3; i++) { float d = v[i] - mean; sq += d * d; }
    #pragma unroll
    for (int o = 16; o > 0; o >>= 1) sq += __shfl_xor_sync(0xffffffffu, sq, o);
    if ((tid & 31) == 0) red[tid >> 5] = sq;
    __syncthreads();
    float var = 0.f;
    #pragma unroll
    for (int i = 0; i < 8; i++) var += red[i];
    var *= (1.0f / E_);
    float inv = rsqrtf(var + EPS_);

    float* yr = y + (long)row * E_;
    #pragma unroll
    for (int i = 0; i < 3; i++) {
        int e = tid + i * 256;
        yr[e] = (v[i] - mean) * inv * g[e] + b[e];
    }
}

// -------------------- GEGLU -------------------------------------------------
__global__ void geglu_kernel(const float* __restrict__ u, float* __restrict__ o) {
    int idx = blockIdx.x * blockDim.x + threadIdx.x;
    if (idx >= L_ * FFN_) return;
    int l = idx / FFN_;
    int f = idx - l * FFN_;
    float a = u[(long)l * (2 * FFN_) + f];
    float g = u[(long)l * (2 * FFN_) + FFN_ + f];
    o[idx] = a * gelu_exact(g);
}

// -------------------- fused flash attention (R7, verified 465us) ------------
#define FBM 64
#define FBN 32

__global__ __launch_bounds__(128, 2)
void flash_attn_kernel(const float* __restrict__ qkv,
                       const int* __restrict__ mask,
                       float* __restrict__ o) {
    __shared__ float Qs[HD_][FBM + 4];
    __shared__ float Ks[HD_][FBN + 2];
    __shared__ float Vs[FBN][HD_ + 4];
    __shared__ float Ps[FBM][FBN + 1];
    __shared__ float kp[FBN];

    int qb  = blockIdx.x;
    int h   = blockIdx.y;
    int tid = threadIdx.x;
    int ty  = tid >> 3;
    int tx  = tid & 7;

    float slope = (h < 8) ? exp2f(-(float)(h + 1))
                          : exp2f(-0.5f * (float)(2 * (h - 8) + 1));
    const float scale = 0.125f;

    #pragma unroll
    for (int r = 0; r < 8; r++) {
        int idx = tid + r * 128;
        int m = idx >> 4;
        int d4 = idx & 15;
        float4 q4 = *(const float4*)(qkv + (long)(qb * FBM + m) * (3 * E_)
                                     + h * HD_ + d4 * 4);
        Qs[d4 * 4 + 0][m] = q4.x * scale;
        Qs[d4 * 4 + 1][m] = q4.y * scale;
        Qs[d4 * 4 + 2][m] = q4.z * scale;
        Qs[d4 * 4 + 3][m] = q4.w * scale;
    }

    float acc[4][8] = {};
    float mi[4], li[4];
    #pragma unroll
    for (int i = 0; i < 4; i++) { mi[i] = -1e30f; li[i] = 0.f; }

    for (int kb = 0; kb < L_ / FBN; kb++) {
        #pragma unroll
        for (int r = 0; r < 4; r++) {
            int idx = tid + r * 128;
            int n = idx >> 4;
            int d4 = idx & 15;
            const float* kb_ = qkv + (long)(kb * FBN + n) * (3 * E_) + E_ + h * HD_;
            float4 k4 = *(const float4*)(kb_ + d4 * 4);
            Ks[d4 * 4 + 0][n] = k4.x; Ks[d4 * 4 + 1][n] = k4.y;
            Ks[d4 * 4 + 2][n] = k4.z; Ks[d4 * 4 + 3][n] = k4.w;
            const float* vb_ = qkv + (long)(kb * FBN + n) * (3 * E_) + 2 * E_ + h * HD_;
            *(float4*)&Vs[n][d4 * 4] = *(const float4*)(vb_ + d4 * 4);
        }
        if (tid < FBN) kp[tid] = (mask[kb * FBN + tid] == 0) ? 1.0f : 0.0f;
        __syncthreads();

        float S[4][4] = {};
        #pragma unroll
        for (int d = 0; d < HD_; d++) {
            float ra[4], rb[4];
            #pragma unroll
            for (int i = 0; i < 4; i++) ra[i] = Qs[d][ty * 4 + i];
            #pragma unroll
            for (int j = 0; j < 4; j++) rb[j] = Ks[d][tx * 4 + j];
            #pragma unroll
            for (int i = 0; i < 4; i++)
                #pragma unroll
                for (int j = 0; j < 4; j++)
                    S[i][j] = fmaf(ra[i], rb[j], S[i][j]);
        }
        #pragma unroll
        for (int i = 0; i < 4; i++) {
            int m = qb * FBM + ty * 4 + i;
            #pragma unroll
            for (int j = 0; j < 4; j++) {
                int n = kb * FBN + tx * 4 + j;
                S[i][j] += slope * (float)(n - m) + kp[tx * 4 + j];
            }
        }
        #pragma unroll
        for (int i = 0; i < 4; i++) {
            float mx = fmaxf(fmaxf(S[i][0], S[i][1]), fmaxf(S[i][2], S[i][3]));
            #pragma unroll
            for (int o2 = 1; o2 < 8; o2 <<= 1)
                mx = fmaxf(mx, __shfl_xor_sync(0xffffffffu, mx, o2));
            float nm = fmaxf(mi[i], mx);
            float corr = __expf(mi[i] - nm);
            float s = 0.f;
            #pragma unroll
            for (int j = 0; j < 4; j++) { S[i][j] = __expf(S[i][j] - nm); s += S[i][j]; }
            #pragma unroll
            for (int o2 = 1; o2 < 8; o2 <<= 1)
                s += __shfl_xor_sync(0xffffffffu, s, o2);
            li[i] = li[i] * corr + s;
            mi[i] = nm;
            #pragma unroll
            for (int j = 0; j < 8; j++) acc[i][j] *= corr;
            #pragma unroll
            for (int j = 0; j < 4; j++) Ps[ty * 4 + i][tx * 4 + j] = S[i][j];
        }
        __syncthreads();

        #pragma unroll
        for (int k = 0; k < FBN; k++) {
            float ra[4], rb[8];
            #pragma unroll
            for (int i = 0; i < 4; i++) ra[i] = Ps[ty * 4 + i][k];
            #pragma unroll
            for (int j = 0; j < 8; j++) rb[j] = Vs[k][tx * 8 + j];
            #pragma unroll
            for (int i = 0; i < 4; i++)
                #pragma unroll
                for (int j = 0; j < 8; j++)
                    acc[i][j] = fmaf(ra[i], rb[j], acc[i][j]);
        }
        __syncthreads();
    }

    #pragma unroll
    for (int i = 0; i < 4; i++) {
        int m = qb * FBM + ty * 4 + i;
        float inv = 1.0f / li[i];
        #pragma unroll
        for (int j = 0; j < 8; j++)
            o[(long)m * E_ + h * HD_ + tx * 8 + j] = acc[i][j] * inv;
    }
}

// -------------------- 3xBF16 tensor-core GEMM (m16n8k16) --------------------
// C[m,n] = sum_k A[m,k] * B[n,k]   (B is (N,K) row-major: "x @ W^T")
// fp32 = bf16_hi + bf16_lo;  C = Ah*Bh + Ah*Bl + Al*Bh (fp32 accum).
// smem stores k-pair-packed uint32 words: word w of row m = (k=2w, k=2w+1).
// epi: 0 = +bias, 1 = +bias+residual, 2 = gelu(+bias)
// Requirements: M % 128 == 0, N % 64 == 0, K % 16 == 0 (all shapes satisfy).
#define TBM 128
#define TBN 64
#define TBK 16

__global__ __launch_bounds__(256, 2)
void gemm_bf16_kernel(const float* __restrict__ A,
                      const float* __restrict__ B,
                      const float* __restrict__ bias,
                      const float* __restrict__ resid,
                      float* __restrict__ C,
                      int M, int N, int K, int epi) {
    // 8 k-pair words per 16-K tile
    __shared__ uint32_t Ah[2][8][TBM + 4];
    __shared__ uint32_t Al[2][8][TBM + 4];
    __shared__ uint32_t Bh[2][8][TBN + 4];
    __shared__ uint32_t Bl[2][8][TBN + 4];

    int tid  = threadIdx.x;
    int lane = tid & 31;
    int wid  = tid >> 5;           // 0..7
    int wm   = (wid & 3) * 32;     // warp row offset in tile
    int wn   = (wid >> 2) * 32;    // warp col offset in tile
    int g    = lane >> 2;          // 0..7
    int tg   = lane & 3;           // 0..3

    int m0 = blockIdx.y * TBM;
    int n0 = blockIdx.x * TBN;

    int arow = tid >> 2;           // 0..63 (A rows arow, arow+64)
    int ac4  = (tid & 3) * 4;      // k-offset (4 elems -> 2 words)
    int aw0  = (tid & 3) * 2;      // word index
    int brow = tid >> 2;           // 0..63 (B row n)

    float acc[2][4][4];
    #pragma unroll
    for (int i = 0; i < 2; i++)
        #pragma unroll
        for (int j = 0; j < 4; j++)
            #pragma unroll
            for (int q = 0; q < 4; q++) acc[i][j][q] = 0.f;

    const int KT = K / TBK;

    // helper lambda-free split of a float4 into hi-words/lo-words
    // ---- load tile 0 ----
    {
        #pragma unroll
        for (int r = 0; r < 2; r++) {
            int m = arow + r * 64;
            float4 v = *(const float4*)(A + (long)(m0 + m) * K + ac4);
            uint32_t hw0 = pack_bf16(v.x, v.y);
            uint32_t hw1 = pack_bf16(v.z, v.w);
            __nv_bfloat162 h01 = *(__nv_bfloat162*)&hw0;
            __nv_bfloat162 h23 = *(__nv_bfloat162*)&hw1;
            uint32_t lw0 = pack_bf16(v.x - __low2float(h01), v.y - __high2float(h01));
            uint32_t lw1 = pack_bf16(v.z - __low2float(h23), v.w - __high2float(h23));
            Ah[0][aw0    ][m] = hw0;  Ah[0][aw0 + 1][m] = hw1;
            Al[0][aw0    ][m] = lw0;  Al[0][aw0 + 1][m] = lw1;
        }
        float4 v = *(const float4*)(B + (long)(n0 + brow) * K + ac4);
        uint32_t hw0 = pack_bf16(v.x, v.y);
        uint32_t hw1 = pack_bf16(v.z, v.w);
        __nv_bfloat162 h01 = *(__nv_bfloat162*)&hw0;
        __nv_bfloat162 h23 = *(__nv_bfloat162*)&hw1;
        uint32_t lw0 = pack_bf16(v.x - __low2float(h01), v.y - __high2float(h01));
        uint32_t lw1 = pack_bf16(v.z - __low2float(h23), v.w - __high2float(h23));
        Bh[0][aw0    ][brow] = hw0;  Bh[0][aw0 + 1][brow] = hw1;
        Bl[0][aw0    ][brow] = lw0;  Bl[0][aw0 + 1][brow] = lw1;
    }
    __syncthreads();

    for (int kt = 0; kt < KT; kt++) {
        int cur = kt & 1;

        // prefetch next tile into registers
        float4 na0, na1, nb;
        if (kt + 1 < KT) {
            int k0 = (kt + 1) * TBK;
            na0 = *(const float4*)(A + (long)(m0 + arow) * K + k0 + ac4);
            na1 = *(const float4*)(A + (long)(m0 + arow + 64) * K + k0 + ac4);
            nb  = *(const float4*)(B + (long)(n0 + brow) * K + k0 + ac4);
        }

        // ---- compute on current tile: one k16 step, 3 passes ----
        {
            uint32_t ah[2][4], al[2][4], bh[4][2], bl[4][2];
            #pragma unroll
            for (int mt = 0; mt < 2; mt++) {
                int m = wm + mt * 16 + g;
                ah[mt][0] = Ah[cur][tg    ][m];
                ah[mt][1] = Ah[cur][tg    ][m + 8];
                ah[mt][2] = Ah[cur][tg + 4][m];
                ah[mt][3] = Ah[cur][tg + 4][m + 8];
                al[mt][0] = Al[cur][tg    ][m];
                al[mt][1] = Al[cur][tg    ][m + 8];
                al[mt][2] = Al[cur][tg + 4][m];
                al[mt][3] = Al[cur][tg + 4][m + 8];
            }
            #pragma unroll
            for (int nt = 0; nt < 4; nt++) {
                int n = wn + nt * 8 + g;
                bh[nt][0] = Bh[cur][tg    ][n];
                bh[nt][1] = Bh[cur][tg + 4][n];
                bl[nt][0] = Bl[cur][tg    ][n];
                bl[nt][1] = Bl[cur][tg + 4][n];
            }
            #pragma unroll
            for (int mt = 0; mt < 2; mt++)
                #pragma unroll
                for (int nt = 0; nt < 4; nt++) {
                    mma_bf16(acc[mt][nt], al[mt], bh[nt]);   // Al*Bh (small)
                    mma_bf16(acc[mt][nt], ah[mt], bl[nt]);   // Ah*Bl (small)
                    mma_bf16(acc[mt][nt], ah[mt], bh[nt]);   // Ah*Bh (main)
                }
        }

        // store prefetched tile into the other buffer
        if (kt + 1 < KT) {
            int nxt = cur ^ 1;
            {
                uint32_t hw0 = pack_bf16(na0.x, na0.y);
                uint32_t hw1 = pack_bf16(na0.z, na0.w);
                __nv_bfloat162 h01 = *(__nv_bfloat162*)&hw0;
                __nv_bfloat162 h23 = *(__nv_bfloat162*)&hw1;
                uint32_t lw0 = pack_bf16(na0.x - __low2float(h01), na0.y - __high2float(h01));
                uint32_t lw1 = pack_bf16(na0.z - __low2float(h23), na0.w - __high2float(h23));
                Ah[nxt][aw0][arow] = hw0;  Ah[nxt][aw0 + 1][arow] = hw1;
                Al[nxt][aw0][arow] = lw0;  Al[nxt][aw0 + 1][arow] = lw1;
            }
            {
                uint32_t hw0 = pack_bf16(na1.x, na1.y);
                uint32_t hw1 = pack_bf16(na1.z, na1.w);
                __nv_bfloat162 h01 = *(__nv_bfloat162*)&hw0;
                __nv_bfloat162 h23 = *(__nv_bfloat162*)&hw1;
                uint32_t lw0 = pack_bf16(na1.x - __low2float(h01), na1.y - __high2float(h01));
                uint32_t lw1 = pack_bf16(na1.z - __low2float(h23), na1.w - __high2float(h23));
                Ah[nxt][aw0][arow + 64] = hw0;  Ah[nxt][aw0 + 1][arow + 64] = hw1;
                Al[nxt][aw0][arow + 64] = lw0;  Al[nxt][aw0 + 1][arow + 64] = lw1;
            }
            {
                uint32_t hw0 = pack_bf16(nb.x, nb.y);
                uint32_t hw1 = pack_bf16(nb.z, nb.w);
                __nv_bfloat162 h01 = *(__nv_bfloat162*)&hw0;
                __nv_bfloat162 h23 = *(__nv_bfloat162*)&hw1;
                uint32_t lw0 = pack_bf16(nb.x - __low2float(h01), nb.y - __high2float(h01));
                uint32_t lw1 = pack_bf16(nb.z - __low2float(h23), nb.w - __high2float(h23));
                Bh[nxt][aw0][brow] = hw0;  Bh[nxt][aw0 + 1][brow] = hw1;
                Bl[nxt][aw0][brow] = lw0;  Bl[nxt][aw0 + 1][brow] = lw1;
            }
            __syncthreads();
        }
    }

    // ---- epilogue (same fragment->C mapping as m16n8k8) ----
    #pragma unroll
    for (int mt = 0; mt < 2; mt++) {
        #pragma unroll
        for (int nt = 0; nt < 4; nt++) {
            int c = n0 + wn + nt * 8 + 2 * tg;
            float b0 = bias[c], b1 = bias[c + 1];
            #pragma unroll
            for (int hf = 0; hf < 2; hf++) {
                int r = m0 + wm + mt * 16 + g + hf * 8;
                float v0 = acc[mt][nt][hf * 2 + 0] + b0;
                float v1 = acc[mt][nt][hf * 2 + 1] + b1;
                if (epi == 1) {
                    v0 += resid[(long)r * N + c];
                    v1 += resid[(long)r * N + c + 1];
                }
                if (epi == 2) { v0 = gelu_exact(v0); v1 = gelu_exact(v1); }
                *(float2*)(C + (long)r * N + c) = make_float2(v0, v1);
            }
        }
    }
}

// ---------------------------------------------------------------------------
extern "C" void kernel_launch(void* const* d_in, const int* in_sizes, int n_in,
                              void* d_out, int out_size) {
    const int*   tokens   = (const int*)  d_in[0];
    const int*   attmask  = (const int*)  d_in[1];
    const float* embed    = (const float*)d_in[2];
    const float* norm1_g  = (const float*)d_in[3];
    const float* norm1_b  = (const float*)d_in[4];
    const float* in_w     = (const float*)d_in[5];
    const float* in_b     = (const float*)d_in[6];
    const float* out_w    = (const float*)d_in[7];
    const float* out_b    = (const float*)d_in[8];
    const float* ffn_g    = (const float*)d_in[9];
    const float* ffn_bt   = (const float*)d_in[10];
    const float* ffn_w1   = (const float*)d_in[11];
    const float* ffn_b1   = (const float*)d_in[12];
    const float* ffn_w2   = (const float*)d_in[13];
    const float* ffn_b2   = (const float*)d_in[14];
    const float* fin_g    = (const float*)d_in[15];
    const float* fin_b    = (const float*)d_in[16];
    const float* mlm_w1   = (const float*)d_in[17];
    const float* mlm_b1   = (const float*)d_in[18];
    const float* mlm_g    = (const float*)d_in[19];
    const float* mlm_bt   = (const float*)d_in[20];
    const float* mlm_w2   = (const float*)d_in[21];
    const float* mlm_b2   = (const float*)d_in[22];
    float* out = (float*)d_out;

    float *x, *h, *tmp, *qkv, *u, *gg;
    cudaGetSymbolAddress((void**)&x,   g_x);
    cudaGetSymbolAddress((void**)&h,   g_h);
    cudaGetSymbolAddress((void**)&tmp, g_tmp);
    cudaGetSymbolAddress((void**)&qkv, g_qkv);
    cudaGetSymbolAddress((void**)&u,   g_u);
    cudaGetSymbolAddress((void**)&gg,  g_gg);

    embed_kernel<<<(L_ * E_ + 255) / 256, 256>>>(tokens, embed, x);

    for (int i = 0; i < NL_; i++) {
        // ---- attention ----
        layernorm_kernel<<<L_, 256>>>(x, norm1_g + i * E_, norm1_b + i * E_, h);

        gemm_bf16_kernel<<<dim3(3 * E_ / TBN, L_ / TBM), 256>>>(
            h, in_w + (long)i * 3 * E_ * E_, in_b + (long)i * 3 * E_,
            nullptr, qkv, L_, 3 * E_, E_, 0);

        flash_attn_kernel<<<dim3(L_ / FBM, H_), 128>>>(qkv, attmask, tmp);

        gemm_bf16_kernel<<<dim3(E_ / TBN, L_ / TBM), 256>>>(
            tmp, out_w + (long)i * E_ * E_, out_b + (long)i * E_,
            x, x, L_, E_, E_, 1);

        // ---- GEGLU FFN ----
        layernorm_kernel<<<L_, 256>>>(x, ffn_g + i * E_, ffn_bt + i * E_, h);

        gemm_bf16_kernel<<<dim3(2 * FFN_ / TBN, L_ / TBM), 256>>>(
            h, ffn_w1 + (long)i * 2 * FFN_ * E_, ffn_b1 + (long)i * 2 * FFN_,
            nullptr, u, L_, 2 * FFN_, E_, 0);

        geglu_kernel<<<(L_ * FFN_ + 255) / 256, 256>>>(u, gg);

        gemm_bf16_kernel<<<dim3(E_ / TBN, L_ / TBM), 256>>>(
            gg, ffn_w2 + (long)i * E_ * FFN_, ffn_b2 + (long)i * E_,
            x, x, L_, E_, FFN_, 1);
    }

    // ---- MLM head ----
    layernorm_kernel<<<L_, 256>>>(x, fin_g, fin_b, h);

    gemm_bf16_kernel<<<dim3(E_ / TBN, L_ / TBM), 256>>>(
        h, mlm_w1, mlm_b1, nullptr, tmp, L_, E_, E_, 2);

    layernorm_kernel<<<L_, 256>>>(tmp, mlm_g, mlm_bt, h);

    gemm_bf16_kernel<<<dim3(V_ / TBN, L_ / TBM), 256>>>(
        h, mlm_w2, mlm_b2, nullptr, out, L_, V_, E_, 0);
}

// round 17
// speedup vs baseline: 2.1591x; 1.2846x over previous
#include <cuda_runtime.h>
#include <cuda_bf16.h>
#include <math.h>
#include <stdint.h>

// ---------------------------------------------------------------------------
// DNABERT2-style encoder forward.
// GEMMs: mma.sync m16n8k16 BF16, 3-pass error-compensated (fp32=hi+lo).
// Attention: tensor-core flash, same bf16 3-pass compensation.
// B=1, L=2048, E=768, H=12, HD=64, NL=4, FFN=2048, V=4096
// ---------------------------------------------------------------------------

#define L_   2048
#define E_   768
#define H_   12
#define HD_  64
#define NL_  4
#define FFN_ 2048
#define V_   4096
#define EPS_ 1e-5f

// -------------------- scratch (static device globals; no allocation) -------
__device__ float g_x   [L_ * E_];
__device__ float g_h   [L_ * E_];
__device__ float g_tmp [L_ * E_];
__device__ float g_qkv [L_ * 3 * E_];
__device__ float g_u   [L_ * 2 * FFN_];
__device__ float g_gg  [L_ * FFN_];

// -------------------- helpers ----------------------------------------------
__device__ __forceinline__ float gelu_exact(float x) {
    return 0.5f * x * (1.0f + erff(x * 0.70710678118654752440f));
}

__device__ __forceinline__ uint32_t pack_bf16(float x, float y) {
    __nv_bfloat162 t = __floats2bfloat162_rn(x, y);   // x -> low half
    return *(uint32_t*)&t;
}

// split (x,y) into hi word + lo word (fp32 = hi + lo per element)
__device__ __forceinline__ void split2(float x, float y, uint32_t& hw, uint32_t& lw) {
    hw = pack_bf16(x, y);
    __nv_bfloat162 b = *(__nv_bfloat162*)&hw;
    lw = pack_bf16(x - __low2float(b), y - __high2float(b));
}

__device__ __forceinline__ void mma_bf16(float* c, const uint32_t* a, const uint32_t* b) {
    asm volatile(
        "mma.sync.aligned.m16n8k16.row.col.f32.bf16.bf16.f32 "
        "{%0,%1,%2,%3}, {%4,%5,%6,%7}, {%8,%9}, {%0,%1,%2,%3};\n"
        : "+f"(c[0]), "+f"(c[1]), "+f"(c[2]), "+f"(c[3])
        : "r"(a[0]), "r"(a[1]), "r"(a[2]), "r"(a[3]), "r"(b[0]), "r"(b[1]));
}

// -------------------- embedding gather --------------------------------------
__global__ void embed_kernel(const int* __restrict__ tokens,
                             const float* __restrict__ embed,
                             float* __restrict__ x) {
    int idx = blockIdx.x * blockDim.x + threadIdx.x;
    if (idx >= L_ * E_) return;
    int l = idx / E_;
    int e = idx - l * E_;
    x[idx] = embed[(long)tokens[l] * E_ + e];
}

// -------------------- layernorm (one block per token) -----------------------
__global__ void layernorm_kernel(const float* __restrict__ x,
                                 const float* __restrict__ g,
                                 const float* __restrict__ b,
                                 float* __restrict__ y) {
    __shared__ float red[32];
    int row = blockIdx.x;
    int tid = threadIdx.x;             // 256 threads
    const float* xr = x + (long)row * E_;
    float v[3];
    #pragma unroll
    for (int i = 0; i < 3; i++) v[i] = xr[tid + i * 256];

    float s = v[0] + v[1] + v[2];
    #pragma unroll
    for (int o = 16; o > 0; o >>= 1) s += __shfl_xor_sync(0xffffffffu, s, o);
    if ((tid & 31) == 0) red[tid >> 5] = s;
    __syncthreads();
    float mean = 0.f;
    #pragma unroll
    for (int i = 0; i < 8; i++) mean += red[i];
    mean *= (1.0f / E_);
    __syncthreads();

    float sq = 0.f;
    #pragma unroll
    for (int i = 0; i < 3; i++) { float d = v[i] - mean; sq += d * d; }
    #pragma unroll
    for (int o = 16; o > 0; o >>= 1) sq += __shfl_xor_sync(0xffffffffu, sq, o);
    if ((tid & 31) == 0) red[tid >> 5] = sq;
    __syncthreads();
    float var = 0.f;
    #pragma unroll
    for (int i = 0; i < 8; i++) var += red[i];
    var *= (1.0f / E_);
    float inv = rsqrtf(var + EPS_);

    float* yr = y + (long)row * E_;
    #pragma unroll
    for (int i = 0; i < 3; i++) {
        int e = tid + i * 256;
        yr[e] = (v[i] - mean) * inv * g[e] + b[e];
    }
}

// -------------------- GEGLU -------------------------------------------------
__global__ void geglu_kernel(const float* __restrict__ u, float* __restrict__ o) {
    int idx = blockIdx.x * blockDim.x + threadIdx.x;
    if (idx >= L_ * FFN_) return;
    int l = idx / FFN_;
    int f = idx - l * FFN_;
    float a = u[(long)l * (2 * FFN_) + f];
    float g = u[(long)l * (2 * FFN_) + FFN_ + f];
    o[idx] = a * gelu_exact(g);
}

// -------------------- tensor-core flash attention ----------------------------
// grid = (L/64, H), 128 threads (4 warps). Q block 64 rows, K-blocks of 64.
// All matmuls: m16n8k16 bf16, 3-pass hi/lo compensated (fp32 accum).
// smem word layout: packed pairs along the mma K dim, array[word][row], RS=72
// (bank = 8*tg+g + const -> conflict-free fragment loads).
// S accumulator (rows g,g+8 / cols 2tg,2tg+1) IS the A-fragment layout for
// PV, so P=exp(S) feeds the PV mma straight from registers.
#define FAM 64
#define FAN 64
#define RS  72
// word-array offsets (in uint32 units): each array 32*RS = 2304 words
#define O_QH 0
#define O_QL 2304
#define O_KH 4608
#define O_KL 6912
#define O_VH 9216
#define O_VL 11520
#define O_KP 13824
#define FA_SMEM ((13824 + 64) * 4)   // 55552 bytes

__global__ __launch_bounds__(128)
void flash_attn_tc_kernel(const float* __restrict__ qkv,
                          const int* __restrict__ mask,
                          float* __restrict__ o) {
    extern __shared__ uint32_t sm[];
    uint32_t* QH = sm + O_QH;  uint32_t* QL = sm + O_QL;
    uint32_t* KH = sm + O_KH;  uint32_t* KL = sm + O_KL;
    uint32_t* VH = sm + O_VH;  uint32_t* VL = sm + O_VL;
    float*    KP = (float*)(sm + O_KP);

    int qb  = blockIdx.x;
    int h   = blockIdx.y;
    int tid = threadIdx.x;
    int lane = tid & 31, wid = tid >> 5;
    int g = lane >> 2, tg = lane & 3;
    int wm = wid * 16;                 // warp's 16 rows within the 64-row tile

    float slope = (h < 8) ? exp2f(-(float)(h + 1))
                          : exp2f(-0.5f * (float)(2 * (h - 8) + 1));
    const float scale = 0.125f;

    // ---- load Q (scaled) once: QH/QL[word dw][m] ----
    {
        int n = tid >> 1, half = tid & 1;
        const float* qrow = qkv + (long)(qb * FAM + n) * (3 * E_) + h * HD_ + half * 32;
        #pragma unroll
        for (int j = 0; j < 8; j++) {
            float4 v = *(const float4*)(qrow + j * 4);
            v.x *= scale; v.y *= scale; v.z *= scale; v.w *= scale;
            int dw = half * 16 + j * 2;
            uint32_t h0, l0, h1, l1;
            split2(v.x, v.y, h0, l0);
            split2(v.z, v.w, h1, l1);
            QH[dw * RS + n] = h0;  QH[(dw + 1) * RS + n] = h1;
            QL[dw * RS + n] = l0;  QL[(dw + 1) * RS + n] = l1;
        }
    }

    float Oacc[8][4];
    #pragma unroll
    for (int i = 0; i < 8; i++)
        #pragma unroll
        for (int j = 0; j < 4; j++) Oacc[i][j] = 0.f;
    float mi[2] = {-1e30f, -1e30f}, li[2] = {0.f, 0.f};

    for (int kb = 0; kb < L_ / FAN; kb++) {
        __syncthreads();   // previous iteration's PV reads done before overwrite

        // ---- K loader: KH/KL[word dw][key n] (packed along d) ----
        {
            int n = tid >> 1, half = tid & 1;
            const float* krow = qkv + (long)(kb * FAN + n) * (3 * E_) + E_ + h * HD_ + half * 32;
            #pragma unroll
            for (int j = 0; j < 8; j++) {
                float4 v = *(const float4*)(krow + j * 4);
                int dw = half * 16 + j * 2;
                uint32_t h0, l0, h1, l1;
                split2(v.x, v.y, h0, l0);
                split2(v.z, v.w, h1, l1);
                KH[dw * RS + n] = h0;  KH[(dw + 1) * RS + n] = h1;
                KL[dw * RS + n] = l0;  KL[(dw + 1) * RS + n] = l1;
            }
        }
        // ---- V loader: VH/VL[word kw][dim d] (packed along keys) ----
        {
            int kw = tid >> 2, qd = (tid & 3) * 16;
            const float* v0 = qkv + (long)(kb * FAN + 2 * kw) * (3 * E_) + 2 * E_ + h * HD_ + qd;
            const float* v1 = v0 + 3 * E_;
            #pragma unroll
            for (int j = 0; j < 4; j++) {
                float4 a = *(const float4*)(v0 + j * 4);
                float4 b = *(const float4*)(v1 + j * 4);
                uint32_t hw, lw;
                split2(a.x, b.x, hw, lw); VH[kw * RS + qd + j * 4 + 0] = hw; VL[kw * RS + qd + j * 4 + 0] = lw;
                split2(a.y, b.y, hw, lw); VH[kw * RS + qd + j * 4 + 1] = hw; VL[kw * RS + qd + j * 4 + 1] = lw;
                split2(a.z, b.z, hw, lw); VH[kw * RS + qd + j * 4 + 2] = hw; VL[kw * RS + qd + j * 4 + 2] = lw;
                split2(a.w, b.w, hw, lw); VH[kw * RS + qd + j * 4 + 3] = hw; VL[kw * RS + qd + j * 4 + 3] = lw;
            }
        }
        if (tid < FAN) KP[tid] = (mask[kb * FAN + tid] == 0) ? 1.0f : 0.0f;
        __syncthreads();

        // ---- S = (scaled Q) @ K^T : 64x64 per block, 16x64 per warp ----
        float S[8][4];
        #pragma unroll
        for (int nt = 0; nt < 8; nt++)
            #pragma unroll
            for (int q = 0; q < 4; q++) S[nt][q] = 0.f;

        #pragma unroll
        for (int ks = 0; ks < 4; ks++) {
            int w0 = (8 * ks + tg) * RS, w1 = (8 * ks + tg + 4) * RS;
            uint32_t ah[4], al[4];
            ah[0] = QH[w0 + wm + g];  ah[1] = QH[w0 + wm + g + 8];
            ah[2] = QH[w1 + wm + g];  ah[3] = QH[w1 + wm + g + 8];
            al[0] = QL[w0 + wm + g];  al[1] = QL[w0 + wm + g + 8];
            al[2] = QL[w1 + wm + g];  al[3] = QL[w1 + wm + g + 8];
            #pragma unroll
            for (int nt = 0; nt < 8; nt++) {
                uint32_t bh[2] = { KH[w0 + nt * 8 + g], KH[w1 + nt * 8 + g] };
                uint32_t bl[2] = { KL[w0 + nt * 8 + g], KL[w1 + nt * 8 + g] };
                mma_bf16(S[nt], al, bh);
                mma_bf16(S[nt], ah, bl);
                mma_bf16(S[nt], ah, bh);
            }
        }

        // ---- bias (alibi + key padding) ----
        int row0 = qb * FAM + wm + g;
        #pragma unroll
        for (int nt = 0; nt < 8; nt++) {
            int c = kb * FAN + nt * 8 + 2 * tg;
            float kp0 = KP[nt * 8 + 2 * tg], kp1 = KP[nt * 8 + 2 * tg + 1];
            S[nt][0] += slope * (float)(c - row0) + kp0;
            S[nt][1] += slope * (float)(c + 1 - row0) + kp1;
            S[nt][2] += slope * (float)(c - (row0 + 8)) + kp0;
            S[nt][3] += slope * (float)(c + 1 - (row0 + 8)) + kp1;
        }

        // ---- online softmax (rows g, g+8; quad shuffles over tg) ----
        float corr[2];
        #pragma unroll
        for (int r = 0; r < 2; r++) {
            float mx = -1e30f;
            #pragma unroll
            for (int nt = 0; nt < 8; nt++)
                mx = fmaxf(mx, fmaxf(S[nt][2 * r], S[nt][2 * r + 1]));
            mx = fmaxf(mx, __shfl_xor_sync(0xffffffffu, mx, 1));
            mx = fmaxf(mx, __shfl_xor_sync(0xffffffffu, mx, 2));
            float nm = fmaxf(mi[r], mx);
            corr[r] = __expf(mi[r] - nm);
            float s = 0.f;
            #pragma unroll
            for (int nt = 0; nt < 8; nt++) {
                S[nt][2 * r]     = __expf(S[nt][2 * r] - nm);
                S[nt][2 * r + 1] = __expf(S[nt][2 * r + 1] - nm);
                s += S[nt][2 * r] + S[nt][2 * r + 1];
            }
            s += __shfl_xor_sync(0xffffffffu, s, 1);
            s += __shfl_xor_sync(0xffffffffu, s, 2);
            li[r] = li[r] * corr[r] + s;
            mi[r] = nm;
        }
        #pragma unroll
        for (int dt = 0; dt < 8; dt++) {
            Oacc[dt][0] *= corr[0];  Oacc[dt][1] *= corr[0];
            Oacc[dt][2] *= corr[1];  Oacc[dt][3] *= corr[1];
        }

        // ---- O += P @ V : P straight from S accumulator registers ----
        #pragma unroll
        for (int kt = 0; kt < 4; kt++) {
            uint32_t ph[4], pl[4];
            split2(S[2 * kt][0],     S[2 * kt][1],     ph[0], pl[0]);
            split2(S[2 * kt][2],     S[2 * kt][3],     ph[1], pl[1]);
            split2(S[2 * kt + 1][0], S[2 * kt + 1][1], ph[2], pl[2]);
            split2(S[2 * kt + 1][2], S[2 * kt + 1][3], ph[3], pl[3]);
            int w0 = (8 * kt + tg) * RS, w1 = (8 * kt + tg + 4) * RS;
            #pragma unroll
            for (int dt = 0; dt < 8; dt++) {
                uint32_t vh[2] = { VH[w0 + dt * 8 + g], VH[w1 + dt * 8 + g] };
                uint32_t vl[2] = { VL[w0 + dt * 8 + g], VL[w1 + dt * 8 + g] };
                mma_bf16(Oacc[dt], pl, vh);
                mma_bf16(Oacc[dt], ph, vl);
                mma_bf16(Oacc[dt], ph, vh);
            }
        }
    }

    // ---- normalize and write ----
    float inv0 = 1.0f / li[0], inv1 = 1.0f / li[1];
    int row0 = qb * FAM + wm + g;
    #pragma unroll
    for (int dt = 0; dt < 8; dt++) {
        int c = h * HD_ + dt * 8 + 2 * tg;
        *(float2*)(o + (long)row0 * E_ + c) =
            make_float2(Oacc[dt][0] * inv0, Oacc[dt][1] * inv0);
        *(float2*)(o + (long)(row0 + 8) * E_ + c) =
            make_float2(Oacc[dt][2] * inv1, Oacc[dt][3] * inv1);
    }
}

// -------------------- 3xBF16 tensor-core GEMM (m16n8k16, verified R16) ------
#define TBM 128
#define TBN 64
#define TBK 16

__global__ __launch_bounds__(256, 2)
void gemm_bf16_kernel(const float* __restrict__ A,
                      const float* __restrict__ B,
                      const float* __restrict__ bias,
                      const float* __restrict__ resid,
                      float* __restrict__ C,
                      int M, int N, int K, int epi) {
    __shared__ uint32_t Ah[2][8][TBM + 4];
    __shared__ uint32_t Al[2][8][TBM + 4];
    __shared__ uint32_t Bh[2][8][TBN + 4];
    __shared__ uint32_t Bl[2][8][TBN + 4];

    int tid  = threadIdx.x;
    int lane = tid & 31;
    int wid  = tid >> 5;
    int wm   = (wid & 3) * 32;
    int wn   = (wid >> 2) * 32;
    int g    = lane >> 2;
    int tg   = lane & 3;

    int m0 = blockIdx.y * TBM;
    int n0 = blockIdx.x * TBN;

    int arow = tid >> 2;
    int ac4  = (tid & 3) * 4;
    int aw0  = (tid & 3) * 2;
    int brow = tid >> 2;

    float acc[2][4][4];
    #pragma unroll
    for (int i = 0; i < 2; i++)
        #pragma unroll
        for (int j = 0; j < 4; j++)
            #pragma unroll
            for (int q = 0; q < 4; q++) acc[i][j][q] = 0.f;

    const int KT = K / TBK;

    {
        #pragma unroll
        for (int r = 0; r < 2; r++) {
            int m = arow + r * 64;
            float4 v = *(const float4*)(A + (long)(m0 + m) * K + ac4);
            uint32_t hw0, lw0, hw1, lw1;
            split2(v.x, v.y, hw0, lw0);
            split2(v.z, v.w, hw1, lw1);
            Ah[0][aw0][m] = hw0;  Ah[0][aw0 + 1][m] = hw1;
            Al[0][aw0][m] = lw0;  Al[0][aw0 + 1][m] = lw1;
        }
        float4 v = *(const float4*)(B + (long)(n0 + brow) * K + ac4);
        uint32_t hw0, lw0, hw1, lw1;
        split2(v.x, v.y, hw0, lw0);
        split2(v.z, v.w, hw1, lw1);
        Bh[0][aw0][brow] = hw0;  Bh[0][aw0 + 1][brow] = hw1;
        Bl[0][aw0][brow] = lw0;  Bl[0][aw0 + 1][brow] = lw1;
    }
    __syncthreads();

    for (int kt = 0; kt < KT; kt++) {
        int cur = kt & 1;

        float4 na0, na1, nb;
        if (kt + 1 < KT) {
            int k0 = (kt + 1) * TBK;
            na0 = *(const float4*)(A + (long)(m0 + arow) * K + k0 + ac4);
            na1 = *(const float4*)(A + (long)(m0 + arow + 64) * K + k0 + ac4);
            nb  = *(const float4*)(B + (long)(n0 + brow) * K + k0 + ac4);
        }

        {
            uint32_t ah[2][4], al[2][4], bh[4][2], bl[4][2];
            #pragma unroll
            for (int mt = 0; mt < 2; mt++) {
                int m = wm + mt * 16 + g;
                ah[mt][0] = Ah[cur][tg    ][m];
                ah[mt][1] = Ah[cur][tg    ][m + 8];
                ah[mt][2] = Ah[cur][tg + 4][m];
                ah[mt][3] = Ah[cur][tg + 4][m + 8];
                al[mt][0] = Al[cur][tg    ][m];
                al[mt][1] = Al[cur][tg    ][m + 8];
                al[mt][2] = Al[cur][tg + 4][m];
                al[mt][3] = Al[cur][tg + 4][m + 8];
            }
            #pragma unroll
            for (int nt = 0; nt < 4; nt++) {
                int n = wn + nt * 8 + g;
                bh[nt][0] = Bh[cur][tg    ][n];
                bh[nt][1] = Bh[cur][tg + 4][n];
                bl[nt][0] = Bl[cur][tg    ][n];
                bl[nt][1] = Bl[cur][tg + 4][n];
            }
            #pragma unroll
            for (int mt = 0; mt < 2; mt++)
                #pragma unroll
                for (int nt = 0; nt < 4; nt++) {
                    mma_bf16(acc[mt][nt], al[mt], bh[nt]);
                    mma_bf16(acc[mt][nt], ah[mt], bl[nt]);
                    mma_bf16(acc[mt][nt], ah[mt], bh[nt]);
                }
        }

        if (kt + 1 < KT) {
            int nxt = cur ^ 1;
            {
                uint32_t hw0, lw0, hw1, lw1;
                split2(na0.x, na0.y, hw0, lw0);
                split2(na0.z, na0.w, hw1, lw1);
                Ah[nxt][aw0][arow] = hw0;  Ah[nxt][aw0 + 1][arow] = hw1;
                Al[nxt][aw0][arow] = lw0;  Al[nxt][aw0 + 1][arow] = lw1;
            }
            {
                uint32_t hw0, lw0, hw1, lw1;
                split2(na1.x, na1.y, hw0, lw0);
                split2(na1.z, na1.w, hw1, lw1);
                Ah[nxt][aw0][arow + 64] = hw0;  Ah[nxt][aw0 + 1][arow + 64] = hw1;
                Al[nxt][aw0][arow + 64] = lw0;  Al[nxt][aw0 + 1][arow + 64] = lw1;
            }
            {
                uint32_t hw0, lw0, hw1, lw1;
                split2(nb.x, nb.y, hw0, lw0);
                split2(nb.z, nb.w, hw1, lw1);
                Bh[nxt][aw0][brow] = hw0;  Bh[nxt][aw0 + 1][brow] = hw1;
                Bl[nxt][aw0][brow] = lw0;  Bl[nxt][aw0 + 1][brow] = lw1;
            }
            __syncthreads();
        }
    }

    #pragma unroll
    for (int mt = 0; mt < 2; mt++) {
        #pragma unroll
        for (int nt = 0; nt < 4; nt++) {
            int c = n0 + wn + nt * 8 + 2 * tg;
            float b0 = bias[c], b1 = bias[c + 1];
            #pragma unroll
            for (int hf = 0; hf < 2; hf++) {
                int r = m0 + wm + mt * 16 + g + hf * 8;
                float v0 = acc[mt][nt][hf * 2 + 0] + b0;
                float v1 = acc[mt][nt][hf * 2 + 1] + b1;
                if (epi == 1) {
                    v0 += resid[(long)r * N + c];
                    v1 += resid[(long)r * N + c + 1];
                }
                if (epi == 2) { v0 = gelu_exact(v0); v1 = gelu_exact(v1); }
                *(float2*)(C + (long)r * N + c) = make_float2(v0, v1);
            }
        }
    }
}

// ---------------------------------------------------------------------------
extern "C" void kernel_launch(void* const* d_in, const int* in_sizes, int n_in,
                              void* d_out, int out_size) {
    const int*   tokens   = (const int*)  d_in[0];
    const int*   attmask  = (const int*)  d_in[1];
    const float* embed    = (const float*)d_in[2];
    const float* norm1_g  = (const float*)d_in[3];
    const float* norm1_b  = (const float*)d_in[4];
    const float* in_w     = (const float*)d_in[5];
    const float* in_b     = (const float*)d_in[6];
    const float* out_w    = (const float*)d_in[7];
    const float* out_b    = (const float*)d_in[8];
    const float* ffn_g    = (const float*)d_in[9];
    const float* ffn_bt   = (const float*)d_in[10];
    const float* ffn_w1   = (const float*)d_in[11];
    const float* ffn_b1   = (const float*)d_in[12];
    const float* ffn_w2   = (const float*)d_in[13];
    const float* ffn_b2   = (const float*)d_in[14];
    const float* fin_g    = (const float*)d_in[15];
    const float* fin_b    = (const float*)d_in[16];
    const float* mlm_w1   = (const float*)d_in[17];
    const float* mlm_b1   = (const float*)d_in[18];
    const float* mlm_g    = (const float*)d_in[19];
    const float* mlm_bt   = (const float*)d_in[20];
    const float* mlm_w2   = (const float*)d_in[21];
    const float* mlm_b2   = (const float*)d_in[22];
    float* out = (float*)d_out;

    float *x, *h, *tmp, *qkv, *u, *gg;
    cudaGetSymbolAddress((void**)&x,   g_x);
    cudaGetSymbolAddress((void**)&h,   g_h);
    cudaGetSymbolAddress((void**)&tmp, g_tmp);
    cudaGetSymbolAddress((void**)&qkv, g_qkv);
    cudaGetSymbolAddress((void**)&u,   g_u);
    cudaGetSymbolAddress((void**)&gg,  g_gg);

    cudaFuncSetAttribute(flash_attn_tc_kernel,
                         cudaFuncAttributeMaxDynamicSharedMemorySize, FA_SMEM);

    embed_kernel<<<(L_ * E_ + 255) / 256, 256>>>(tokens, embed, x);

    for (int i = 0; i < NL_; i++) {
        // ---- attention ----
        layernorm_kernel<<<L_, 256>>>(x, norm1_g + i * E_, norm1_b + i * E_, h);

        gemm_bf16_kernel<<<dim3(3 * E_ / TBN, L_ / TBM), 256>>>(
            h, in_w + (long)i * 3 * E_ * E_, in_b + (long)i * 3 * E_,
            nullptr, qkv, L_, 3 * E_, E_, 0);

        flash_attn_tc_kernel<<<dim3(L_ / FAM, H_), 128, FA_SMEM>>>(qkv, attmask, tmp);

        gemm_bf16_kernel<<<dim3(E_ / TBN, L_ / TBM), 256>>>(
            tmp, out_w + (long)i * E_ * E_, out_b + (long)i * E_,
            x, x, L_, E_, E_, 1);

        // ---- GEGLU FFN ----
        layernorm_kernel<<<L_, 256>>>(x, ffn_g + i * E_, ffn_bt + i * E_, h);

        gemm_bf16_kernel<<<dim3(2 * FFN_ / TBN, L_ / TBM), 256>>>(
            h, ffn_w1 + (long)i * 2 * FFN_ * E_, ffn_b1 + (long)i * 2 * FFN_,
            nullptr, u, L_, 2 * FFN_, E_, 0);

        geglu_kernel<<<(L_ * FFN_ + 255) / 256, 256>>>(u, gg);

        gemm_bf16_kernel<<<dim3(E_ / TBN, L_ / TBM), 256>>>(
            gg, ffn_w2 + (long)i * E_ * FFN_, ffn_b2 + (long)i * E_,
            x, x, L_, E_, FFN_, 1);
    }

    // ---- MLM head ----
    layernorm_kernel<<<L_, 256>>>(x, fin_g, fin_b, h);

    gemm_bf16_kernel<<<dim3(E_ / TBN, L_ / TBM), 256>>>(
        h, mlm_w1, mlm_b1, nullptr, tmp, L_, E_, E_, 2);

    layernorm_kernel<<<L_, 256>>>(tmp, mlm_g, mlm_bt, h);

    gemm_bf16_kernel<<<dim3(V_ / TBN, L_ / TBM), 256>>>(
        h, mlm_w2, mlm_b2, nullptr, out, L_, V_, E_, 0);
}